// round 7
// baseline (speedup 1.0000x reference)
#include <cuda_runtime.h>
#include <cuda_bf16.h>
#include <cstdint>

typedef unsigned long long u64;
typedef long long i64;
typedef uint32_t u32;

#define EPS 1e-5f

// ---------------- scratch (device globals; no runtime alloc) ----------------
__device__ __align__(16) u32   S1[600000u * 128];   // packed bf16-split activations
__device__ __align__(16) u32   S2[600000u * 128];
__device__ __align__(16) float S3[600000u * 60];    // preds [n][k][60]
__device__ __align__(16) float S4[600000];          // cls logits
__device__ __align__(16) float S5[100000u * 128];   // actors @ agt_W[128:256] (fp32)
__device__ __align__(16) u32   XP[100000u * 128];   // actors packed
__device__ __align__(16) u32   WIMG[17 * 16384];    // packed W, [n][k] per matrix

// ---------------- helpers ----------------------------------------------------
__device__ __forceinline__ u32 packbf(float x) {
    u32 hb = (u32)__bfloat16_as_ushort(__float2bfloat16(x));
    float r = x - __uint_as_float(hb << 16);
    return (hb << 16) | (u32)__bfloat16_as_ushort(__float2bfloat16(r));
}
__device__ __forceinline__ float unpackf(u32 w) {
    return __uint_as_float(w & 0xffff0000u) + __uint_as_float(w << 16);
}
__device__ __forceinline__ void mma16816(float* c, const u32* a, const u32* b) {
    asm volatile(
        "mma.sync.aligned.m16n8k16.row.col.f32.bf16.bf16.f32 "
        "{%0,%1,%2,%3}, {%4,%5,%6,%7}, {%8,%9}, {%0,%1,%2,%3};"
        : "+f"(c[0]), "+f"(c[1]), "+f"(c[2]), "+f"(c[3])
        : "r"(a[0]), "r"(a[1]), "r"(a[2]), "r"(a[3]), "r"(b[0]), "r"(b[1]));
}
__device__ __forceinline__ u32 bph(uint2 q) { return __byte_perm(q.x, q.y, 0x7632); }
__device__ __forceinline__ u32 bpl(uint2 q) { return __byte_perm(q.x, q.y, 0x5410); }

__device__ __forceinline__ u32 smem_u32p(const void* p) {
    u32 a;
    asm("{ .reg .u64 t; cvta.to.shared.u64 t, %1; cvt.u32.u64 %0, t; }" : "=r"(a) : "l"(p));
    return a;
}
__device__ __forceinline__ void cpa16(u32 dst, const void* src, int sz) {
    asm volatile("cp.async.ca.shared.global [%0], [%1], 16, %2;"
                 :: "r"(dst), "l"(src), "r"(sz) : "memory");
}
#define CPA_COMMIT() asm volatile("cp.async.commit_group;" ::: "memory")
#define CPA_WAIT0()  asm volatile("cp.async.wait_group 0;" ::: "memory")

// ---------------- weight prep: transpose + pack -----------------------------
__global__ void prep_w(const float* pW1, const float* pW2, const float* dW1,
                       const float* aW, const float* cW1, const float* cW2)
{
    int id = blockIdx.x;
    const float* W;
    if      (id < 6)   W = pW1 + id * 16384;
    else if (id < 12)  W = pW2 + (id - 6) * 16384;
    else if (id == 12) W = dW1;
    else if (id == 13) W = aW;               // agt_W rows 0..127
    else if (id == 14) W = aW + 16384;       // agt_W rows 128..255
    else if (id == 15) W = cW1;
    else               W = cW2;
    u32* dst = WIMG + id * 16384;
    for (int idx = threadIdx.x; idx < 16384; idx += blockDim.x) {
        int n = idx >> 7, k = idx & 127;
        dst[idx] = packbf(W[k * 128 + n]);   // B[n][k] = W[k][n]
    }
}

__global__ void prep_x(const float* a, u32* dst, int n) {
    int i = blockIdx.x * blockDim.x + threadIdx.x;
    if (i < n) dst[i] = packbf(a[i]);
}

// ---------------- tensor GEMM: 64-row tile, 2 CTAs/SM ------------------------
struct TGP {
    const u32* A;  i64 A_k;                 // packed activations (u32 elems)
    const u32* Wimg; i64 W_k;               // packed W [n][k] (u32 elems)
    const float* g; const float* b; i64 gb_k;
    float* outF; i64 outF_k;
    u32* outP;   i64 outP_k;
    const float* pre;                       // pre-GN add, row = grow/6
    const float* post; i64 post_k;          // post-GN add, row = grow
    const float* wo; const float* wob; float* dot;
    const float* genP; const float* W0; const float* b0;   // dist A-gen
    int M, gn, relu;
};

#define RSU 132                       // A/W smem row stride (u32)
#define CSTR 130                      // C smem row stride (floats)
#define OF_W  4096
#define OF_A  (OF_W + 128 * RSU * 4)          // 71680
#define TG_SMEM (OF_A + 64 * RSU * 4)         // 105472

__global__ void __launch_bounds__(256, 2) tgemm(TGP p) {
    extern __shared__ char smc[];
    float* gv  = (float*)smc;           // 128
    float* bv  = gv + 128;              // 128
    float* wv  = bv + 128;              // 128
    float* w0a = wv + 128;              // 128
    float* w0b = w0a + 128;             // 128
    float* b0v = w0b + 128;             // 128
    float* pav = b0v + 128;             // 64
    float* pbv = pav + 64;              // 64
    u32* Wp = (u32*)(smc + OF_W);
    u32* Ap = (u32*)(smc + OF_A);
    float* Cs = (float*)(smc + OF_A);   // overlays A after MMA
    const u32 sbase = smem_u32p(smc);

    const int tid = threadIdx.x, wid = tid >> 5, lane = tid & 31;
    const int y = blockIdx.y;
    const int row0 = blockIdx.x * 64;
    const int wm = wid >> 2, wn = wid & 3;
    const int g = lane >> 2, tg = lane & 3;

    // ---- stage W (4096 uint4) + A (2048 uint4) via cp.async ----
    {
        const u32* Wg = p.Wimg + (size_t)p.W_k * y;
        #pragma unroll
        for (int i = 0; i < 16; i++) {
            int idx = tid + 256 * i;
            int r = idx >> 5, c = (idx & 31) * 4;
            cpa16(sbase + OF_W + (r * RSU + c) * 4, Wg + r * 128 + c, 16);
        }
    }
    if (!p.genP) {
        const u32* Ag = p.A + (size_t)p.A_k * y;
        #pragma unroll
        for (int i = 0; i < 8; i++) {
            int idx = tid + 256 * i;
            int r = idx >> 5, c = (idx & 31) * 4;
            int gr = row0 + r;
            cpa16(sbase + OF_A + (r * RSU + c) * 4,
                  Ag + (size_t)(gr < p.M ? gr : 0) * 128 + c, gr < p.M ? 16 : 0);
        }
    }
    CPA_COMMIT();

    if (tid < 128) {
        if (p.gn) { gv[tid] = p.g[p.gb_k * y + tid]; bv[tid] = p.b[p.gb_k * y + tid]; }
        if (p.wo) wv[tid] = p.wo[tid];
        if (p.genP) { w0a[tid] = p.W0[tid]; w0b[tid] = p.W0[128 + tid]; b0v[tid] = p.b0[tid]; }
    }
    if (p.genP && tid < 64) {
        int gr = row0 + tid; float a = 0.f, bq = 0.f;
        if (gr < p.M) { a = p.genP[(size_t)gr * 60 + 58]; bq = p.genP[(size_t)gr * 60 + 59]; }
        pav[tid] = a; pbv[tid] = bq;
    }
    CPA_WAIT0();
    __syncthreads();

    if (p.genP) {
        #pragma unroll
        for (int it = 0; it < 32; it++) {
            int idx = tid + it * 256;
            int r = idx >> 7, k = idx & 127;
            Ap[r * RSU + k] = packbf(fmaxf(b0v[k] - pav[r] * w0a[k] - pbv[r] * w0b[k], 0.f));
        }
        __syncthreads();
    }

    // ---- MMA: 8 warps, 2x4 grid, warp tile 32x32, 3-term split ----
    float acc[2][4][4];
    #pragma unroll
    for (int i = 0; i < 2; i++)
        #pragma unroll
        for (int j = 0; j < 4; j++)
            #pragma unroll
            for (int q = 0; q < 4; q++) acc[i][j][q] = 0.f;

    #pragma unroll
    for (int ks = 0; ks < 8; ks++) {
        const int kc = ks * 16 + tg * 2;
        u32 ah[2][4], al[2][4];
        #pragma unroll
        for (int mt = 0; mt < 2; mt++) {
            const u32* ap = Ap + (wm * 32 + mt * 16 + g) * RSU + kc;
            uint2 q0 = *(const uint2*)ap;
            uint2 q1 = *(const uint2*)(ap + 8 * RSU);
            uint2 q2 = *(const uint2*)(ap + 8);
            uint2 q3 = *(const uint2*)(ap + 8 * RSU + 8);
            ah[mt][0] = bph(q0); ah[mt][1] = bph(q1); ah[mt][2] = bph(q2); ah[mt][3] = bph(q3);
            al[mt][0] = bpl(q0); al[mt][1] = bpl(q1); al[mt][2] = bpl(q2); al[mt][3] = bpl(q3);
        }
        u32 bh[4][2], bl[4][2];
        #pragma unroll
        for (int nt = 0; nt < 4; nt++) {
            const u32* wp = Wp + (wn * 32 + nt * 8 + g) * RSU + kc;
            uint2 r0 = *(const uint2*)wp;
            uint2 r1 = *(const uint2*)(wp + 8);
            bh[nt][0] = bph(r0); bh[nt][1] = bph(r1);
            bl[nt][0] = bpl(r0); bl[nt][1] = bpl(r1);
        }
        #pragma unroll
        for (int mt = 0; mt < 2; mt++)
            #pragma unroll
            for (int nt = 0; nt < 4; nt++) {
                mma16816(acc[mt][nt], ah[mt], bh[nt]);
                mma16816(acc[mt][nt], al[mt], bh[nt]);
                mma16816(acc[mt][nt], ah[mt], bl[nt]);
            }
    }
    __syncthreads();                 // A reads done -> reuse as C

    #pragma unroll
    for (int mt = 0; mt < 2; mt++) {
        int r0 = wm * 32 + mt * 16 + g;
        #pragma unroll
        for (int nt = 0; nt < 4; nt++) {
            int c0 = wn * 32 + nt * 8 + tg * 2;
            *(float2*)(Cs + (size_t)r0 * CSTR + c0)       = make_float2(acc[mt][nt][0], acc[mt][nt][1]);
            *(float2*)(Cs + (size_t)(r0 + 8) * CSTR + c0) = make_float2(acc[mt][nt][2], acc[mt][nt][3]);
        }
    }
    __syncthreads();

    // ---- epilogue: 4 threads/row, 32 cols each, two passes, no reg arrays ----
    const int erow = tid >> 2, eq = tid & 3;
    const int grow = row0 + erow;
    const bool ok = grow < p.M;
    const float2* Cr = (const float2*)(Cs + (size_t)erow * CSTR + eq * 32);
    const float* prerow = (p.pre && ok) ? p.pre + (size_t)(grow / 6) * 128 + eq * 32 : nullptr;

    float mval = 0.f, inv = 1.f;
    if (p.gn) {
        float s = 0.f, ss = 0.f;
        #pragma unroll
        for (int j = 0; j < 16; j++) {
            float2 a = Cr[j];
            if (prerow) { a.x += prerow[2 * j]; a.y += prerow[2 * j + 1]; }
            s += a.x + a.y; ss += a.x * a.x + a.y * a.y;
        }
        s  += __shfl_xor_sync(~0u, s, 1);  ss += __shfl_xor_sync(~0u, ss, 1);
        s  += __shfl_xor_sync(~0u, s, 2);  ss += __shfl_xor_sync(~0u, ss, 2);
        mval = s * (1.f / 128.f);
        inv = rsqrtf(ss * (1.f / 128.f) - mval * mval + EPS);
    }

    float v[32];
    #pragma unroll
    for (int j = 0; j < 16; j++) {
        float2 a = Cr[j];
        if (prerow) { a.x += prerow[2 * j]; a.y += prerow[2 * j + 1]; }
        v[2 * j] = a.x; v[2 * j + 1] = a.y;
    }
    if (p.gn) {
        #pragma unroll
        for (int j = 0; j < 32; j++)
            v[j] = (v[j] - mval) * inv * gv[eq * 32 + j] + bv[eq * 32 + j];
    }
    if (p.post && ok) {
        const float4* q = (const float4*)(p.post + p.post_k * y + (size_t)grow * 128 + eq * 32);
        #pragma unroll
        for (int j = 0; j < 8; j++) {
            float4 a = q[j];
            v[4*j] += a.x; v[4*j+1] += a.y; v[4*j+2] += a.z; v[4*j+3] += a.w;
        }
    }
    if (p.relu) {
        #pragma unroll
        for (int j = 0; j < 32; j++) v[j] = fmaxf(v[j], 0.f);
    }
    if (p.wo) {
        float d = 0.f;
        #pragma unroll
        for (int j = 0; j < 32; j++) d += v[j] * wv[eq * 32 + j];
        d += __shfl_xor_sync(~0u, d, 1);
        d += __shfl_xor_sync(~0u, d, 2);
        if (eq == 0 && ok) p.dot[grow] = d + p.wob[0];
    }
    if (p.outF && ok) {
        float4* dq = (float4*)(p.outF + p.outF_k * y + (size_t)grow * 128 + eq * 32);
        #pragma unroll
        for (int j = 0; j < 8; j++) dq[j] = make_float4(v[4*j], v[4*j+1], v[4*j+2], v[4*j+3]);
    }
    if (p.outP && ok) {
        uint4* dq = (uint4*)(p.outP + p.outP_k * y + (size_t)grow * 128 + eq * 32);
        #pragma unroll
        for (int j = 0; j < 8; j++)
            dq[j] = make_uint4(packbf(v[4*j]), packbf(v[4*j+1]), packbf(v[4*j+2]), packbf(v[4*j+3]));
    }
}

// ---------------- Wo head (FFMA2): [M,128] @ [128,60] + bias ----------------
#define SAW 130
__device__ __forceinline__ void fma2(u64& d, u64 a, u64 b) {
    asm("fma.rn.f32x2 %0, %1, %2, %0;" : "+l"(d) : "l"(a), "l"(b));
}
__device__ __forceinline__ u64 pk(float x) {
    u64 r; asm("mov.b64 %0, {%1, %1};" : "=l"(r) : "f"(x)); return r;
}
__device__ __forceinline__ void up2(float& lo, float& hi, u64 v) {
    asm("mov.b64 {%0, %1}, %2;" : "=f"(lo), "=f"(hi) : "l"(v));
}

__global__ void __launch_bounds__(256, 1) gemm_wo(
    const u32* A, i64 A_k, const float* W, i64 W_k,
    const float* bo, float* out, int M)
{
    extern __shared__ float sm[];
    float* As = sm;               // [128][SAW] transposed fp32 A tile
    float* Ws = As + 128 * SAW;   // [128][64]
    float* bb = Ws + 128 * 64;

    const int tid = threadIdx.x, y = blockIdx.y, row0 = blockIdx.x * 128;
    const float* Wg = W + W_k * y;
    out += y * 60;

    for (int idx = tid; idx < 128 * 64; idx += 256) {
        int r = idx >> 6, c = idx & 63;
        Ws[idx] = (c < 60) ? Wg[r * 60 + c] : 0.f;
    }
    if (tid < 64) bb[tid] = (tid < 60) ? bo[y * 60 + tid] : 0.f;

    const u32* Ag = A + (size_t)A_k * y;
    #pragma unroll
    for (int it = 0; it < 16; it++) {
        int idx = tid + it * 256;
        int r = idx >> 5, c4 = (idx & 31) * 4, gr = row0 + r;
        uint4 w = make_uint4(0u, 0u, 0u, 0u);
        if (gr < M) w = ((const uint4*)(Ag + (size_t)gr * 128))[idx & 31];
        As[(c4    ) * SAW + r] = unpackf(w.x);
        As[(c4 + 1) * SAW + r] = unpackf(w.y);
        As[(c4 + 2) * SAW + r] = unpackf(w.z);
        As[(c4 + 3) * SAW + r] = unpackf(w.w);
    }
    __syncthreads();

    const int rg = tid >> 4, cg = tid & 15;
    u64 acc[4][4];
    #pragma unroll
    for (int i = 0; i < 4; i++)
        #pragma unroll
        for (int j = 0; j < 4; j++) acc[i][j] = 0ull;

    #pragma unroll 4
    for (int k = 0; k < 128; k++) {
        const u64* ap = (const u64*)(As + k * SAW + rg * 8);
        u64 a0 = ap[0], a1 = ap[1], a2 = ap[2], a3 = ap[3];
        float4 q = *(const float4*)(Ws + k * 64 + cg * 4);
        u64 b0 = pk(q.x), b1 = pk(q.y), b2 = pk(q.z), b3 = pk(q.w);
        fma2(acc[0][0], a0, b0); fma2(acc[0][1], a0, b1); fma2(acc[0][2], a0, b2); fma2(acc[0][3], a0, b3);
        fma2(acc[1][0], a1, b0); fma2(acc[1][1], a1, b1); fma2(acc[1][2], a1, b2); fma2(acc[1][3], a1, b3);
        fma2(acc[2][0], a2, b0); fma2(acc[2][1], a2, b1); fma2(acc[2][2], a2, b2); fma2(acc[2][3], a2, b3);
        fma2(acc[3][0], a3, b0); fma2(acc[3][1], a3, b1); fma2(acc[3][2], a3, b2); fma2(acc[3][3], a3, b3);
    }

    #pragma unroll
    for (int i = 0; i < 4; i++) {
        int rl = row0 + rg * 8 + 2 * i, rh = rl + 1;
        #pragma unroll
        for (int j = 0; j < 4; j++) {
            int c = cg * 4 + j;
            float lo, hi; up2(lo, hi, acc[i][j]);
            if (c < 60) {
                if (rl < M) out[(size_t)rl * 360 + c] = lo + bb[c];
                if (rh < M) out[(size_t)rh * 360 + c] = hi + bb[c];
            }
        }
    }
}

// ---------------- softmax + rank-sort + reg gather (warp per actor) ---------
__global__ void finalize(const float* preds, const float* lg, const float* ctr,
                         float* clsO, float* regO, int N)
{
    int w = (blockIdx.x * blockDim.x + threadIdx.x) >> 5;
    int lane = threadIdx.x & 31;
    if (w >= N) return;
    float v = (lane < 6) ? lg[(size_t)w * 6 + lane] : -3.4e38f;
    float m = v;
    #pragma unroll
    for (int s = 4; s >= 1; s >>= 1) m = fmaxf(m, __shfl_xor_sync(~0u, m, s));
    float e = (lane < 6) ? expf(v - m) : 0.f;
    float s = e;
    #pragma unroll
    for (int t = 4; t >= 1; t >>= 1) s += __shfl_xor_sync(~0u, s, t);
    float pr = e / s;
    int rk = 0;
    #pragma unroll
    for (int j = 0; j < 6; j++) {
        float pj = __shfl_sync(~0u, pr, j);
        rk += (pj > pr) || (pj == pr && j < lane);
    }
    if (lane < 6) clsO[(size_t)w * 6 + rk] = pr;
    float cx = ctr[(size_t)w * 2], cy = ctr[(size_t)w * 2 + 1];
    for (int k = 0; k < 6; k++) {
        int r = __shfl_sync(~0u, rk, k);
        const float* sp = preds + (size_t)w * 360 + k * 60;
        float* dp = regO + ((size_t)w * 6 + r) * 60;
        for (int j = lane; j < 60; j += 32) dp[j] = sp[j] + ((j & 1) ? cy : cx);
    }
}

// ---------------- host orchestration ----------------------------------------
extern "C" void kernel_launch(void* const* d_in, const int* in_sizes, int n_in,
                              void* d_out, int out_size)
{
    const float* actors = (const float*)d_in[0];
    const float* ctrs   = (const float*)d_in[1];
    const float* pW1 = (const float*)d_in[2];
    const float* pg1 = (const float*)d_in[3];
    const float* pb1 = (const float*)d_in[4];
    const float* pW2 = (const float*)d_in[5];
    const float* pg2 = (const float*)d_in[6];
    const float* pb2 = (const float*)d_in[7];
    const float* pWo = (const float*)d_in[8];
    const float* pbo = (const float*)d_in[9];
    const float* dW0 = (const float*)d_in[10];
    const float* db0 = (const float*)d_in[11];
    const float* dW1 = (const float*)d_in[12];
    const float* dg1 = (const float*)d_in[13];
    const float* db1 = (const float*)d_in[14];
    const float* aW  = (const float*)d_in[15];
    const float* ag  = (const float*)d_in[16];
    const float* ab  = (const float*)d_in[17];
    const float* cW1 = (const float*)d_in[18];
    const float* cg1 = (const float*)d_in[19];
    const float* cb1 = (const float*)d_in[20];
    const float* cW2 = (const float*)d_in[21];
    const float* cg2 = (const float*)d_in[22];
    const float* cb2 = (const float*)d_in[23];
    const float* cWo = (const float*)d_in[24];
    const float* cbo = (const float*)d_in[25];

    u32 *s1, *s2, *xp, *wimg; float *s3, *s4, *s5;
    cudaGetSymbolAddress((void**)&s1, S1);
    cudaGetSymbolAddress((void**)&s2, S2);
    cudaGetSymbolAddress((void**)&s3, S3);
    cudaGetSymbolAddress((void**)&s4, S4);
    cudaGetSymbolAddress((void**)&s5, S5);
    cudaGetSymbolAddress((void**)&xp, XP);
    cudaGetSymbolAddress((void**)&wimg, WIMG);

    const int N = in_sizes[0] / 128;       // 100000
    const int M = N * 6;
    const int gN = (N + 63) / 64, gM = (M + 63) / 64;
    const int tilesN = (N + 127) / 128;
    float* out   = (float*)d_out;
    float* regO  = out + (size_t)N * 6;
    float* feats = regO + (size_t)N * 360;

    cudaFuncSetAttribute(tgemm, cudaFuncAttributeMaxDynamicSharedMemorySize, TG_SMEM);
    const size_t shW = (size_t)(128 * SAW + 128 * 64 + 64) * 4;
    cudaFuncSetAttribute(gemm_wo, cudaFuncAttributeMaxDynamicSharedMemorySize, (int)shW);

    prep_w<<<17, 128>>>(pW1, pW2, dW1, aW, cW1, cW2);
    prep_x<<<(N * 128 + 255) / 256, 256>>>(actors, xp, N * 128);

    TGP q;

    // L1: actB = actors @ agt_W[128:256] -> S5 fp32
    q = TGP{}; q.A = xp; q.Wimg = wimg + 14 * 16384; q.outF = s5; q.M = N;
    tgemm<<<dim3(gN, 1), 256, TG_SMEM>>>(q);

    // L2: h1 = relu(gn(actors @ pred_W1)) -> S1 packed (mode-major)
    q = TGP{}; q.A = xp; q.Wimg = wimg; q.W_k = 16384;
    q.g = pg1; q.b = pb1; q.gb_k = 128;
    q.outP = s1; q.outP_k = (i64)N * 128; q.M = N; q.gn = 1; q.relu = 1;
    tgemm<<<dim3(gN, 6), 256, TG_SMEM>>>(q);

    // L3: h = relu(gn(h1 @ pred_W2) + actors) -> S1 in-place
    q = TGP{}; q.A = s1; q.A_k = (i64)N * 128; q.Wimg = wimg + 6 * 16384; q.W_k = 16384;
    q.g = pg2; q.b = pb2; q.gb_k = 128; q.post = actors;
    q.outP = s1; q.outP_k = (i64)N * 128; q.M = N; q.gn = 1; q.relu = 1;
    tgemm<<<dim3(gN, 6), 256, TG_SMEM>>>(q);

    // L4: preds = h @ pred_Wo + bo -> S3 [n][k][60]
    gemm_wo<<<dim3(tilesN, 6), 256, shW>>>(s1, (i64)N * 128, pWo, 128 * 60, pbo, s3, N);

    // L5: dh2 = relu(gn(gen(dist) @ dist_W1)) -> S1 packed [M]
    q = TGP{}; q.genP = s3; q.W0 = dW0; q.b0 = db0; q.Wimg = wimg + 12 * 16384;
    q.g = dg1; q.b = db1; q.outP = s1; q.M = M; q.gn = 1; q.relu = 1;
    tgemm<<<dim3(gM, 1), 256, TG_SMEM>>>(q);

    // L6: feats = relu(gn(dh2 @ agt_W[0:128] + actB)) -> feats fp32 + S2 packed
    q = TGP{}; q.A = s1; q.Wimg = wimg + 13 * 16384; q.g = ag; q.b = ab; q.pre = s5;
    q.outF = feats; q.outP = s2; q.M = M; q.gn = 1; q.relu = 1;
    tgemm<<<dim3(gM, 1), 256, TG_SMEM>>>(q);

    // L7: c1 = relu(gn(feats @ cls_W1)) -> S1 packed
    q = TGP{}; q.A = s2; q.Wimg = wimg + 15 * 16384; q.g = cg1; q.b = cb1;
    q.outP = s1; q.M = M; q.gn = 1; q.relu = 1;
    tgemm<<<dim3(gM, 1), 256, TG_SMEM>>>(q);

    // L8: c = relu(gn(c1 @ cls_W2) + feats); logits = c @ cls_Wo + cbo -> S4
    q = TGP{}; q.A = s1; q.Wimg = wimg + 16 * 16384; q.g = cg2; q.b = cb2;
    q.post = feats; q.wo = cWo; q.wob = cbo; q.dot = s4; q.M = M; q.gn = 1; q.relu = 1;
    tgemm<<<dim3(gM, 1), 256, TG_SMEM>>>(q);

    // L9: softmax + sort + gather
    finalize<<<(N + 7) / 8, 256>>>(s3, s4, ctrs, out, regO, N);
}

// round 9
// speedup vs baseline: 1.0735x; 1.0735x over previous
#include <cuda_runtime.h>
#include <cuda_bf16.h>
#include <cstdint>

typedef unsigned long long u64;
typedef long long i64;
typedef uint32_t u32;

#define EPS 1e-5f

// ---------------- scratch (device globals; no runtime alloc) ----------------
__device__ __align__(16) u32   S1[600000u * 128];   // packed bf16-split activations
__device__ __align__(16) u32   S2[600000u * 128];
__device__ __align__(16) float S3[600000u * 60];    // preds [n][k][60]
__device__ __align__(16) float S4[600000];          // cls logits
__device__ __align__(16) float S5[100000u * 128];   // actors @ agt_W[128:256] (fp32)
__device__ __align__(16) u32   XP[100000u * 128];   // actors packed
__device__ __align__(16) u32   WIMG[17 * 16384];    // packed W, [n][k] per matrix

// ---------------- helpers ----------------------------------------------------
__device__ __forceinline__ u32 packbf(float x) {
    u32 hb = (u32)__bfloat16_as_ushort(__float2bfloat16(x));
    float r = x - __uint_as_float(hb << 16);
    return (hb << 16) | (u32)__bfloat16_as_ushort(__float2bfloat16(r));
}
__device__ __forceinline__ float unpackf(u32 w) {
    return __uint_as_float(w & 0xffff0000u) + __uint_as_float(w << 16);
}
__device__ __forceinline__ void mma16816(float* c, const u32* a, const u32* b) {
    asm volatile(
        "mma.sync.aligned.m16n8k16.row.col.f32.bf16.bf16.f32 "
        "{%0,%1,%2,%3}, {%4,%5,%6,%7}, {%8,%9}, {%0,%1,%2,%3};"
        : "+f"(c[0]), "+f"(c[1]), "+f"(c[2]), "+f"(c[3])
        : "r"(a[0]), "r"(a[1]), "r"(a[2]), "r"(a[3]), "r"(b[0]), "r"(b[1]));
}
__device__ __forceinline__ void ldsm4(u32& r0, u32& r1, u32& r2, u32& r3, u32 addr) {
    asm volatile("ldmatrix.sync.aligned.m8n8.x4.shared.b16 {%0,%1,%2,%3}, [%4];"
                 : "=r"(r0), "=r"(r1), "=r"(r2), "=r"(r3) : "r"(addr));
}
__device__ __forceinline__ u32 bph(u32 x, u32 y) { return __byte_perm(x, y, 0x7632); }
__device__ __forceinline__ u32 bpl(u32 x, u32 y) { return __byte_perm(x, y, 0x5410); }

__device__ __forceinline__ u32 smem_u32p(const void* p) {
    u32 a;
    asm("{ .reg .u64 t; cvta.to.shared.u64 t, %1; cvt.u32.u64 %0, t; }" : "=r"(a) : "l"(p));
    return a;
}

// ---------------- weight prep: transpose + pack -----------------------------
__global__ void prep_w(const float* pW1, const float* pW2, const float* dW1,
                       const float* aW, const float* cW1, const float* cW2)
{
    int id = blockIdx.x;
    const float* W;
    if      (id < 6)   W = pW1 + id * 16384;
    else if (id < 12)  W = pW2 + (id - 6) * 16384;
    else if (id == 12) W = dW1;
    else if (id == 13) W = aW;               // agt_W rows 0..127
    else if (id == 14) W = aW + 16384;       // agt_W rows 128..255
    else if (id == 15) W = cW1;
    else               W = cW2;
    u32* dst = WIMG + id * 16384;
    for (int idx = threadIdx.x; idx < 16384; idx += blockDim.x) {
        int n = idx >> 7, k = idx & 127;
        dst[idx] = packbf(W[k * 128 + n]);   // B[n][k] = W[k][n]
    }
}

__global__ void prep_x(const float* a, u32* dst, int n) {
    int i = blockIdx.x * blockDim.x + threadIdx.x;
    if (i < n) dst[i] = packbf(a[i]);
}

// ---------------- tensor GEMM: 128x128 tile, ldmatrix fragments --------------
struct TGP {
    const u32* A;  i64 A_k;                 // packed activations (u32 elems)
    const u32* Wimg; i64 W_k;               // packed W [n][k] (u32 elems)
    const float* g; const float* b; i64 gb_k;
    float* outF; i64 outF_k;
    u32* outP;   i64 outP_k;
    const float* pre;                       // pre-GN add, row = grow/6
    const float* post; i64 post_k;          // post-GN add, row = grow
    const float* wo; const float* wob; float* dot;
    const float* genP; const float* W0; const float* b0;   // dist A-gen
    int M, gn, relu;
};

#define RSB 272                       // plane row stride (bytes); 272/4 = 68 = 4 mod 32
#define PLANE (128 * RSB)             // 34816
#define CSTR 130                      // C smem row stride (floats)
#define OF_AH 4096
#define OF_AL (OF_AH + PLANE)
#define OF_WH (OF_AL + PLANE)
#define OF_WL (OF_WH + PLANE)
#define TG_SMEM (OF_WL + PLANE)       // 143360

__global__ void __launch_bounds__(256, 1) tgemm(TGP p) {
    extern __shared__ char smc[];
    float* gv  = (float*)smc;           // 128
    float* bv  = gv + 128;              // 128
    float* wv  = bv + 128;              // 128
    float* w0a = wv + 128;              // 128
    float* w0b = w0a + 128;             // 128
    float* b0v = w0b + 128;             // 128
    float* pav = b0v + 128;             // 128
    float* pbv = pav + 128;             // 128  (total 4096 B)
    char* Ahi = smc + OF_AH;
    char* Alo = smc + OF_AL;
    char* Whi = smc + OF_WH;
    char* Wlo = smc + OF_WL;
    float* Cs = (float*)(smc + OF_AH);  // overlays A planes after MMA
    const u32 sbase = smem_u32p(smc);

    const int tid = threadIdx.x, wid = tid >> 5, lane = tid & 31;
    const int y = blockIdx.y;
    const int row0 = blockIdx.x * 128;
    const int wm = wid >> 2, wn = wid & 3;
    const int g = lane >> 2, tg = lane & 3;

    // ---- stage W planes: LDG packed uint4, split, STS uint2 per plane ----
    {
        const u32* Wg = p.Wimg + (size_t)p.W_k * y;
        #pragma unroll
        for (int i = 0; i < 16; i++) {
            int idx = tid + 256 * i;             // 4096 uint4
            int r = idx >> 5, c4 = (idx & 31) * 4;
            uint4 v = ((const uint4*)(Wg + r * 128))[idx & 31];
            int off = r * RSB + c4 * 2;
            *(uint2*)(Whi + off) = make_uint2(bph(v.x, v.y), bph(v.z, v.w));
            *(uint2*)(Wlo + off) = make_uint2(bpl(v.x, v.y), bpl(v.z, v.w));
        }
    }
    if (tid < 128) {
        if (p.gn) { gv[tid] = p.g[p.gb_k * y + tid]; bv[tid] = p.b[p.gb_k * y + tid]; }
        if (p.wo) wv[tid] = p.wo[tid];
        if (p.genP) {
            w0a[tid] = p.W0[tid]; w0b[tid] = p.W0[128 + tid]; b0v[tid] = p.b0[tid];
            int gr = row0 + tid; float a = 0.f, bq = 0.f;
            if (gr < p.M) { a = p.genP[(size_t)gr * 60 + 58]; bq = p.genP[(size_t)gr * 60 + 59]; }
            pav[tid] = a; pbv[tid] = bq;
        }
    }

    // ---- stage A planes ----
    if (p.genP) {
        __syncthreads();
        #pragma unroll
        for (int it = 0; it < 32; it++) {
            int idx = tid + it * 256;            // 8192: row x 64 k-pairs
            int r = idx >> 6, k2 = (idx & 63) * 2;
            float x0 = fmaxf(b0v[k2]     - pav[r] * w0a[k2]     - pbv[r] * w0b[k2],     0.f);
            float x1 = fmaxf(b0v[k2 + 1] - pav[r] * w0a[k2 + 1] - pbv[r] * w0b[k2 + 1], 0.f);
            u32 p0 = packbf(x0), p1 = packbf(x1);
            int off = r * RSB + k2 * 2;
            *(u32*)(Ahi + off) = (p0 >> 16) | (p1 & 0xffff0000u);
            *(u32*)(Alo + off) = (p0 & 0xffffu) | (p1 << 16);
        }
    } else {
        const u32* Ag = p.A + (size_t)p.A_k * y;
        #pragma unroll
        for (int i = 0; i < 16; i++) {
            int idx = tid + 256 * i;
            int r = idx >> 5, c4 = (idx & 31) * 4;
            int gr = row0 + r;
            uint4 v = make_uint4(0u, 0u, 0u, 0u);
            if (gr < p.M) v = ((const uint4*)(Ag + (size_t)gr * 128))[idx & 31];
            int off = r * RSB + c4 * 2;
            *(uint2*)(Ahi + off) = make_uint2(bph(v.x, v.y), bph(v.z, v.w));
            *(uint2*)(Alo + off) = make_uint2(bpl(v.x, v.y), bpl(v.z, v.w));
        }
    }
    __syncthreads();

    // ---- MMA: 8 warps, 2x4 grid, warp tile 64x32, 3-term split, ldmatrix ----
    float acc[4][4][4];
    #pragma unroll
    for (int i = 0; i < 4; i++)
        #pragma unroll
        for (int j = 0; j < 4; j++)
            #pragma unroll
            for (int q = 0; q < 4; q++) acc[i][j][q] = 0.f;

    // lane -> ldmatrix row/col selects
    const int lr = lane & 15;             // row within 16
    const int lc = (lane >> 4) * 16;      // byte col select (0 or 16)
    const u32 aoff = (u32)((wm * 64 + lr) * RSB + lc);
    const u32 boff = (u32)((wn * 32 + lr) * RSB + lc);

    #pragma unroll
    for (int ks = 0; ks < 8; ks++) {
        const u32 kb = ks * 32;           // 16 k * 2B
        u32 ah[4][4], al[4][4];
        #pragma unroll
        for (int mt = 0; mt < 4; mt++) {
            ldsm4(ah[mt][0], ah[mt][1], ah[mt][2], ah[mt][3],
                  sbase + OF_AH + aoff + (u32)(mt * 16 * RSB) + kb);
            ldsm4(al[mt][0], al[mt][1], al[mt][2], al[mt][3],
                  sbase + OF_AL + aoff + (u32)(mt * 16 * RSB) + kb);
        }
        // B: one x4 covers two nt (16 n rows x 16 k)
        u32 bh[4][2], bl[4][2];
        #pragma unroll
        for (int pp = 0; pp < 2; pp++) {
            u32 r0, r1, r2, r3;
            ldsm4(r0, r1, r2, r3, sbase + OF_WH + boff + (u32)(pp * 16 * RSB) + kb);
            bh[2*pp][0] = r0; bh[2*pp][1] = r2; bh[2*pp+1][0] = r1; bh[2*pp+1][1] = r3;
            ldsm4(r0, r1, r2, r3, sbase + OF_WL + boff + (u32)(pp * 16 * RSB) + kb);
            bl[2*pp][0] = r0; bl[2*pp][1] = r2; bl[2*pp+1][0] = r1; bl[2*pp+1][1] = r3;
        }
        #pragma unroll
        for (int mt = 0; mt < 4; mt++)
            #pragma unroll
            for (int nt = 0; nt < 4; nt++) {
                mma16816(acc[mt][nt], ah[mt], bh[nt]);
                mma16816(acc[mt][nt], al[mt], bh[nt]);
                mma16816(acc[mt][nt], ah[mt], bl[nt]);
            }
    }
    __syncthreads();                 // A reads done -> reuse as C

    #pragma unroll
    for (int mt = 0; mt < 4; mt++) {
        int r0 = wm * 64 + mt * 16 + g;
        #pragma unroll
        for (int nt = 0; nt < 4; nt++) {
            int c0 = wn * 32 + nt * 8 + tg * 2;
            *(float2*)(Cs + (size_t)r0 * CSTR + c0)       = make_float2(acc[mt][nt][0], acc[mt][nt][1]);
            *(float2*)(Cs + (size_t)(r0 + 8) * CSTR + c0) = make_float2(acc[mt][nt][2], acc[mt][nt][3]);
        }
    }
    __syncthreads();

    // ---- epilogue: two passes of 64 rows; 4 threads/row x 32 cols ----
    #pragma unroll 1
    for (int ep = 0; ep < 2; ep++) {
        const int erow = ep * 64 + (tid >> 2), eq = tid & 3;
        const int grow = row0 + erow;
        const bool ok = grow < p.M;
        const float2* Cr = (const float2*)(Cs + (size_t)erow * CSTR + eq * 32);
        const float* prerow = (p.pre && ok) ? p.pre + (size_t)(grow / 6) * 128 + eq * 32 : nullptr;

        float v[32];
        #pragma unroll
        for (int j = 0; j < 16; j++) {
            float2 a = Cr[j];
            if (prerow) { a.x += prerow[2 * j]; a.y += prerow[2 * j + 1]; }
            v[2 * j] = a.x; v[2 * j + 1] = a.y;
        }
        if (p.gn) {
            float s = 0.f, ss = 0.f;
            #pragma unroll
            for (int j = 0; j < 32; j++) { s += v[j]; ss += v[j] * v[j]; }
            s  += __shfl_xor_sync(~0u, s, 1);  ss += __shfl_xor_sync(~0u, ss, 1);
            s  += __shfl_xor_sync(~0u, s, 2);  ss += __shfl_xor_sync(~0u, ss, 2);
            float m = s * (1.f / 128.f);
            float inv = rsqrtf(ss * (1.f / 128.f) - m * m + EPS);
            #pragma unroll
            for (int j = 0; j < 32; j++)
                v[j] = (v[j] - m) * inv * gv[eq * 32 + j] + bv[eq * 32 + j];
        }
        if (p.post && ok) {
            const float4* q = (const float4*)(p.post + p.post_k * y + (size_t)grow * 128 + eq * 32);
            #pragma unroll
            for (int j = 0; j < 8; j++) {
                float4 a = q[j];
                v[4*j] += a.x; v[4*j+1] += a.y; v[4*j+2] += a.z; v[4*j+3] += a.w;
            }
        }
        if (p.relu) {
            #pragma unroll
            for (int j = 0; j < 32; j++) v[j] = fmaxf(v[j], 0.f);
        }
        if (p.wo) {
            float d = 0.f;
            #pragma unroll
            for (int j = 0; j < 32; j++) d += v[j] * wv[eq * 32 + j];
            d += __shfl_xor_sync(~0u, d, 1);
            d += __shfl_xor_sync(~0u, d, 2);
            if (eq == 0 && ok) p.dot[grow] = d + p.wob[0];
        }
        if (p.outF && ok) {
            float4* dq = (float4*)(p.outF + p.outF_k * y + (size_t)grow * 128 + eq * 32);
            #pragma unroll
            for (int j = 0; j < 8; j++) dq[j] = make_float4(v[4*j], v[4*j+1], v[4*j+2], v[4*j+3]);
        }
        if (p.outP && ok) {
            uint4* dq = (uint4*)(p.outP + p.outP_k * y + (size_t)grow * 128 + eq * 32);
            #pragma unroll
            for (int j = 0; j < 8; j++)
                dq[j] = make_uint4(packbf(v[4*j]), packbf(v[4*j+1]), packbf(v[4*j+2]), packbf(v[4*j+3]));
        }
    }
}

// ---------------- Wo head (FFMA2): [M,128] @ [128,60] + bias ----------------
#define SAW 130
__device__ __forceinline__ void fma2(u64& d, u64 a, u64 b) {
    asm("fma.rn.f32x2 %0, %1, %2, %0;" : "+l"(d) : "l"(a), "l"(b));
}
__device__ __forceinline__ u64 pk(float x) {
    u64 r; asm("mov.b64 %0, {%1, %1};" : "=l"(r) : "f"(x)); return r;
}
__device__ __forceinline__ void up2(float& lo, float& hi, u64 v) {
    asm("mov.b64 {%0, %1}, %2;" : "=f"(lo), "=f"(hi) : "l"(v));
}

__global__ void __launch_bounds__(256, 1) gemm_wo(
    const u32* A, i64 A_k, const float* W, i64 W_k,
    const float* bo, float* out, int M)
{
    extern __shared__ float sm[];
    float* As = sm;               // [128][SAW] transposed fp32 A tile
    float* Ws = As + 128 * SAW;   // [128][64]
    float* bb = Ws + 128 * 64;

    const int tid = threadIdx.x, y = blockIdx.y, row0 = blockIdx.x * 128;
    const float* Wg = W + W_k * y;
    out += y * 60;

    for (int idx = tid; idx < 128 * 64; idx += 256) {
        int r = idx >> 6, c = idx & 63;
        Ws[idx] = (c < 60) ? Wg[r * 60 + c] : 0.f;
    }
    if (tid < 64) bb[tid] = (tid < 60) ? bo[y * 60 + tid] : 0.f;

    const u32* Ag = A + (size_t)A_k * y;
    #pragma unroll
    for (int it = 0; it < 16; it++) {
        int idx = tid + it * 256;
        int r = idx >> 5, c4 = (idx & 31) * 4, gr = row0 + r;
        uint4 w = make_uint4(0u, 0u, 0u, 0u);
        if (gr < M) w = ((const uint4*)(Ag + (size_t)gr * 128))[idx & 31];
        As[(c4    ) * SAW + r] = unpackf(w.x);
        As[(c4 + 1) * SAW + r] = unpackf(w.y);
        As[(c4 + 2) * SAW + r] = unpackf(w.z);
        As[(c4 + 3) * SAW + r] = unpackf(w.w);
    }
    __syncthreads();

    const int rg = tid >> 4, cg = tid & 15;
    u64 acc[4][4];
    #pragma unroll
    for (int i = 0; i < 4; i++)
        #pragma unroll
        for (int j = 0; j < 4; j++) acc[i][j] = 0ull;

    #pragma unroll 4
    for (int k = 0; k < 128; k++) {
        const u64* ap = (const u64*)(As + k * SAW + rg * 8);
        u64 a0 = ap[0], a1 = ap[1], a2 = ap[2], a3 = ap[3];
        float4 q = *(const float4*)(Ws + k * 64 + cg * 4);
        u64 b0 = pk(q.x), b1 = pk(q.y), b2 = pk(q.z), b3 = pk(q.w);
        fma2(acc[0][0], a0, b0); fma2(acc[0][1], a0, b1); fma2(acc[0][2], a0, b2); fma2(acc[0][3], a0, b3);
        fma2(acc[1][0], a1, b0); fma2(acc[1][1], a1, b1); fma2(acc[1][2], a1, b2); fma2(acc[1][3], a1, b3);
        fma2(acc[2][0], a2, b0); fma2(acc[2][1], a2, b1); fma2(acc[2][2], a2, b2); fma2(acc[2][3], a2, b3);
        fma2(acc[3][0], a3, b0); fma2(acc[3][1], a3, b1); fma2(acc[3][2], a3, b2); fma2(acc[3][3], a3, b3);
    }

    #pragma unroll
    for (int i = 0; i < 4; i++) {
        int rl = row0 + rg * 8 + 2 * i, rh = rl + 1;
        #pragma unroll
        for (int j = 0; j < 4; j++) {
            int c = cg * 4 + j;
            float lo, hi; up2(lo, hi, acc[i][j]);
            if (c < 60) {
                if (rl < M) out[(size_t)rl * 360 + c] = lo + bb[c];
                if (rh < M) out[(size_t)rh * 360 + c] = hi + bb[c];
            }
        }
    }
}

// ---------------- softmax + rank-sort + reg gather (warp per actor) ---------
__global__ void finalize(const float* preds, const float* lg, const float* ctr,
                         float* clsO, float* regO, int N)
{
    int w = (blockIdx.x * blockDim.x + threadIdx.x) >> 5;
    int lane = threadIdx.x & 31;
    if (w >= N) return;
    float v = (lane < 6) ? lg[(size_t)w * 6 + lane] : -3.4e38f;
    float m = v;
    #pragma unroll
    for (int s = 4; s >= 1; s >>= 1) m = fmaxf(m, __shfl_xor_sync(~0u, m, s));
    float e = (lane < 6) ? expf(v - m) : 0.f;
    float s = e;
    #pragma unroll
    for (int t = 4; t >= 1; t >>= 1) s += __shfl_xor_sync(~0u, s, t);
    float pr = e / s;
    int rk = 0;
    #pragma unroll
    for (int j = 0; j < 6; j++) {
        float pj = __shfl_sync(~0u, pr, j);
        rk += (pj > pr) || (pj == pr && j < lane);
    }
    if (lane < 6) clsO[(size_t)w * 6 + rk] = pr;
    float cx = ctr[(size_t)w * 2], cy = ctr[(size_t)w * 2 + 1];
    for (int k = 0; k < 6; k++) {
        int r = __shfl_sync(~0u, rk, k);
        const float* sp = preds + (size_t)w * 360 + k * 60;
        float* dp = regO + ((size_t)w * 6 + r) * 60;
        for (int j = lane; j < 60; j += 32) dp[j] = sp[j] + ((j & 1) ? cy : cx);
    }
}

// ---------------- host orchestration ----------------------------------------
extern "C" void kernel_launch(void* const* d_in, const int* in_sizes, int n_in,
                              void* d_out, int out_size)
{
    const float* actors = (const float*)d_in[0];
    const float* ctrs   = (const float*)d_in[1];
    const float* pW1 = (const float*)d_in[2];
    const float* pg1 = (const float*)d_in[3];
    const float* pb1 = (const float*)d_in[4];
    const float* pW2 = (const float*)d_in[5];
    const float* pg2 = (const float*)d_in[6];
    const float* pb2 = (const float*)d_in[7];
    const float* pWo = (const float*)d_in[8];
    const float* pbo = (const float*)d_in[9];
    const float* dW0 = (const float*)d_in[10];
    const float* db0 = (const float*)d_in[11];
    const float* dW1 = (const float*)d_in[12];
    const float* dg1 = (const float*)d_in[13];
    const float* db1 = (const float*)d_in[14];
    const float* aW  = (const float*)d_in[15];
    const float* ag  = (const float*)d_in[16];
    const float* ab  = (const float*)d_in[17];
    const float* cW1 = (const float*)d_in[18];
    const float* cg1 = (const float*)d_in[19];
    const float* cb1 = (const float*)d_in[20];
    const float* cW2 = (const float*)d_in[21];
    const float* cg2 = (const float*)d_in[22];
    const float* cb2 = (const float*)d_in[23];
    const float* cWo = (const float*)d_in[24];
    const float* cbo = (const float*)d_in[25];

    u32 *s1, *s2, *xp, *wimg; float *s3, *s4, *s5;
    cudaGetSymbolAddress((void**)&s1, S1);
    cudaGetSymbolAddress((void**)&s2, S2);
    cudaGetSymbolAddress((void**)&s3, S3);
    cudaGetSymbolAddress((void**)&s4, S4);
    cudaGetSymbolAddress((void**)&s5, S5);
    cudaGetSymbolAddress((void**)&xp, XP);
    cudaGetSymbolAddress((void**)&wimg, WIMG);

    const int N = in_sizes[0] / 128;       // 100000
    const int M = N * 6;
    const int gN = (N + 127) / 128, gM = (M + 127) / 128;
    float* out   = (float*)d_out;
    float* regO  = out + (size_t)N * 6;
    float* feats = regO + (size_t)N * 360;

    cudaFuncSetAttribute(tgemm, cudaFuncAttributeMaxDynamicSharedMemorySize, TG_SMEM);
    const size_t shW = (size_t)(128 * SAW + 128 * 64 + 64) * 4;
    cudaFuncSetAttribute(gemm_wo, cudaFuncAttributeMaxDynamicSharedMemorySize, (int)shW);

    prep_w<<<17, 128>>>(pW1, pW2, dW1, aW, cW1, cW2);
    prep_x<<<(N * 128 + 255) / 256, 256>>>(actors, xp, N * 128);

    TGP q;

    // L1: actB = actors @ agt_W[128:256] -> S5 fp32
    q = TGP{}; q.A = xp; q.Wimg = wimg + 14 * 16384; q.outF = s5; q.M = N;
    tgemm<<<dim3(gN, 1), 256, TG_SMEM>>>(q);

    // L2: h1 = relu(gn(actors @ pred_W1)) -> S1 packed (mode-major)
    q = TGP{}; q.A = xp; q.Wimg = wimg; q.W_k = 16384;
    q.g = pg1; q.b = pb1; q.gb_k = 128;
    q.outP = s1; q.outP_k = (i64)N * 128; q.M = N; q.gn = 1; q.relu = 1;
    tgemm<<<dim3(gN, 6), 256, TG_SMEM>>>(q);

    // L3: h = relu(gn(h1 @ pred_W2) + actors) -> S1 in-place
    q = TGP{}; q.A = s1; q.A_k = (i64)N * 128; q.Wimg = wimg + 6 * 16384; q.W_k = 16384;
    q.g = pg2; q.b = pb2; q.gb_k = 128; q.post = actors;
    q.outP = s1; q.outP_k = (i64)N * 128; q.M = N; q.gn = 1; q.relu = 1;
    tgemm<<<dim3(gN, 6), 256, TG_SMEM>>>(q);

    // L4: preds = h @ pred_Wo + bo -> S3 [n][k][60]
    gemm_wo<<<dim3(gN, 6), 256, shW>>>(s1, (i64)N * 128, pWo, 128 * 60, pbo, s3, N);

    // L5: dh2 = relu(gn(gen(dist) @ dist_W1)) -> S1 packed [M]
    q = TGP{}; q.genP = s3; q.W0 = dW0; q.b0 = db0; q.Wimg = wimg + 12 * 16384;
    q.g = dg1; q.b = db1; q.outP = s1; q.M = M; q.gn = 1; q.relu = 1;
    tgemm<<<dim3(gM, 1), 256, TG_SMEM>>>(q);

    // L6: feats = relu(gn(dh2 @ agt_W[0:128] + actB)) -> feats fp32 + S2 packed
    q = TGP{}; q.A = s1; q.Wimg = wimg + 13 * 16384; q.g = ag; q.b = ab; q.pre = s5;
    q.outF = feats; q.outP = s2; q.M = M; q.gn = 1; q.relu = 1;
    tgemm<<<dim3(gM, 1), 256, TG_SMEM>>>(q);

    // L7: c1 = relu(gn(feats @ cls_W1)) -> S1 packed
    q = TGP{}; q.A = s2; q.Wimg = wimg + 15 * 16384; q.g = cg1; q.b = cb1;
    q.outP = s1; q.M = M; q.gn = 1; q.relu = 1;
    tgemm<<<dim3(gM, 1), 256, TG_SMEM>>>(q);

    // L8: c = relu(gn(c1 @ cls_W2) + feats); logits = c @ cls_Wo + cbo -> S4
    q = TGP{}; q.A = s1; q.Wimg = wimg + 16 * 16384; q.g = cg2; q.b = cb2;
    q.post = feats; q.wo = cWo; q.wob = cbo; q.dot = s4; q.M = M; q.gn = 1; q.relu = 1;
    tgemm<<<dim3(gM, 1), 256, TG_SMEM>>>(q);

    // L9: softmax + sort + gather
    finalize<<<(N + 7) / 8, 256>>>(s3, s4, ctrs, out, regO, N);
}

// round 11
// speedup vs baseline: 1.5237x; 1.4194x over previous
#include <cuda_runtime.h>
#include <cuda_bf16.h>
#include <cstdint>

typedef unsigned long long u64;
typedef long long i64;
typedef uint32_t u32;

#define EPS 1e-5f
#define RS 272                      // plane row stride (bytes)
#define PLANE (128 * RS)            // 34816
#define VECB 8192
#define OF_AH VECB
#define OF_AL (OF_AH + PLANE)
#define OF_WH (OF_AL + PLANE)
#define OF_WL (OF_WH + PLANE)
#define SMEMB (OF_WL + PLANE)       // 147456
#define CSTR 132

// ---------------- scratch (device globals; no runtime alloc) ----------------
__device__ __align__(16) u32   XP[100000u * 128];   // actors packed
__device__ __align__(16) u32   WIMG[17 * 16384];    // packed W [n][k]
__device__ __align__(16) u32   WOIMG[6 * 8192];     // packed Wo [o(64)][k]
__device__ __align__(16) float S3[600000u * 60];    // preds [n*6+k][60]
__device__ __align__(16) float S4[600000];          // cls logits
__device__ __align__(16) float S5[100000u * 128];   // actB fp32

// ---------------- helpers ----------------------------------------------------
__device__ __forceinline__ u32 packbf(float x) {
    u32 hb = (u32)__bfloat16_as_ushort(__float2bfloat16(x));
    float r = x - __uint_as_float(hb << 16);
    return (hb << 16) | (u32)__bfloat16_as_ushort(__float2bfloat16(r));
}
__device__ __forceinline__ void mma16816(float* c, const u32* a, const u32* b) {
    asm volatile(
        "mma.sync.aligned.m16n8k16.row.col.f32.bf16.bf16.f32 "
        "{%0,%1,%2,%3}, {%4,%5,%6,%7}, {%8,%9}, {%0,%1,%2,%3};"
        : "+f"(c[0]), "+f"(c[1]), "+f"(c[2]), "+f"(c[3])
        : "r"(a[0]), "r"(a[1]), "r"(a[2]), "r"(a[3]), "r"(b[0]), "r"(b[1]));
}
__device__ __forceinline__ u32 bph(u32 x, u32 y) { return __byte_perm(x, y, 0x7632); }
__device__ __forceinline__ u32 bpl(u32 x, u32 y) { return __byte_perm(x, y, 0x5410); }

// ---------------- prep kernels ----------------------------------------------
__global__ void prep_w(const float* pW1, const float* pW2, const float* dW1,
                       const float* aW, const float* cW1, const float* cW2)
{
    int id = blockIdx.x;
    const float* W;
    if      (id < 6)   W = pW1 + id * 16384;
    else if (id < 12)  W = pW2 + (id - 6) * 16384;
    else if (id == 12) W = dW1;
    else if (id == 13) W = aW;
    else if (id == 14) W = aW + 16384;
    else if (id == 15) W = cW1;
    else               W = cW2;
    u32* dst = WIMG + id * 16384;
    for (int idx = threadIdx.x; idx < 16384; idx += blockDim.x) {
        int n = idx >> 7, k = idx & 127;
        dst[idx] = packbf(W[k * 128 + n]);
    }
}
__global__ void prep_wo(const float* pWo) {
    int y = blockIdx.x;
    u32* dst = WOIMG + y * 8192;
    for (int idx = threadIdx.x; idx < 8192; idx += blockDim.x) {
        int o = idx >> 7, k = idx & 127;
        float x = (o < 60) ? pWo[y * 7680 + k * 60 + o] : 0.f;
        dst[idx] = packbf(x);
    }
}
__global__ void prep_x(const float* a, int n) {
    int i = blockIdx.x * blockDim.x + threadIdx.x;
    if (i < n) XP[i] = packbf(a[i]);
}

// ---------------- staging device functions -----------------------------------
__device__ __forceinline__ void stageW128(const u32* src, char* hi, char* lo, int tid) {
    #pragma unroll
    for (int i = 0; i < 16; i++) {
        int idx = tid + 256 * i;
        int r = idx >> 5, c4 = (idx & 31) * 4;
        uint4 v = ((const uint4*)(src + r * 128))[idx & 31];
        int off = r * RS + c4 * 2;
        *(uint2*)(hi + off) = make_uint2(bph(v.x, v.y), bph(v.z, v.w));
        *(uint2*)(lo + off) = make_uint2(bpl(v.x, v.y), bpl(v.z, v.w));
    }
}
__device__ __forceinline__ void stageW64(const u32* src, char* hi, char* lo, int tid) {
    #pragma unroll
    for (int i = 0; i < 8; i++) {
        int idx = tid + 256 * i;
        int r = idx >> 5, c4 = (idx & 31) * 4;
        uint4 v = ((const uint4*)(src + r * 128))[idx & 31];
        int off = r * RS + c4 * 2;
        *(uint2*)(hi + off) = make_uint2(bph(v.x, v.y), bph(v.z, v.w));
        *(uint2*)(lo + off) = make_uint2(bpl(v.x, v.y), bpl(v.z, v.w));
    }
}
__device__ __forceinline__ void stageA(const u32* Ag, char* hi, char* lo, int tid, int row0, int M) {
    #pragma unroll
    for (int i = 0; i < 16; i++) {
        int idx = tid + 256 * i;
        int r = idx >> 5, c4 = (idx & 31) * 4;
        int gr = row0 + r;
        uint4 v = make_uint4(0u, 0u, 0u, 0u);
        if (gr < M) v = ((const uint4*)(Ag + (size_t)gr * 128))[idx & 31];
        int off = r * RS + c4 * 2;
        *(uint2*)(hi + off) = make_uint2(bph(v.x, v.y), bph(v.z, v.w));
        *(uint2*)(lo + off) = make_uint2(bpl(v.x, v.y), bpl(v.z, v.w));
    }
}

// ---------------- MMA + C store (R5-proven layout) ---------------------------
template <int MT>
__device__ __forceinline__ void mma_tile(const char* Ahi, const char* Alo,
    const char* Whi, const char* Wlo, int rbase, int nbase, int g, int tg,
    float (&acc)[MT][4][4])
{
    #pragma unroll
    for (int i = 0; i < MT; i++)
        #pragma unroll
        for (int j = 0; j < 4; j++)
            #pragma unroll
            for (int q = 0; q < 4; q++) acc[i][j][q] = 0.f;

    #pragma unroll
    for (int ks = 0; ks < 8; ks++) {
        const int cA = (ks * 16 + tg * 2) * 2;
        u32 ah[MT][4], al[MT][4];
        #pragma unroll
        for (int mt = 0; mt < MT; mt++) {
            int rb = (rbase + mt * 16 + g) * RS;
            ah[mt][0] = *(const u32*)(Ahi + rb + cA);
            ah[mt][1] = *(const u32*)(Ahi + rb + 8 * RS + cA);
            ah[mt][2] = *(const u32*)(Ahi + rb + cA + 16);
            ah[mt][3] = *(const u32*)(Ahi + rb + 8 * RS + cA + 16);
            al[mt][0] = *(const u32*)(Alo + rb + cA);
            al[mt][1] = *(const u32*)(Alo + rb + 8 * RS + cA);
            al[mt][2] = *(const u32*)(Alo + rb + cA + 16);
            al[mt][3] = *(const u32*)(Alo + rb + 8 * RS + cA + 16);
        }
        u32 bh[4][2], bl[4][2];
        #pragma unroll
        for (int nt = 0; nt < 4; nt++) {
            int nb = (nbase + nt * 8 + g) * RS;
            bh[nt][0] = *(const u32*)(Whi + nb + cA);
            bh[nt][1] = *(const u32*)(Whi + nb + cA + 16);
            bl[nt][0] = *(const u32*)(Wlo + nb + cA);
            bl[nt][1] = *(const u32*)(Wlo + nb + cA + 16);
        }
        #pragma unroll
        for (int mt = 0; mt < MT; mt++)
            #pragma unroll
            for (int nt = 0; nt < 4; nt++) {
                mma16816(acc[mt][nt], ah[mt], bh[nt]);
                mma16816(acc[mt][nt], al[mt], bh[nt]);
                mma16816(acc[mt][nt], ah[mt], bl[nt]);
            }
    }
}
template <int MT>
__device__ __forceinline__ void store_C(float* Cs, int rbase, int nbase, int g, int tg,
                                        float (&acc)[MT][4][4])
{
    #pragma unroll
    for (int mt = 0; mt < MT; mt++) {
        int r0 = rbase + mt * 16 + g;
        #pragma unroll
        for (int nt = 0; nt < 4; nt++) {
            int c0 = nbase + nt * 8 + tg * 2;
            *(float2*)(Cs + (size_t)r0 * CSTR + c0)       = make_float2(acc[mt][nt][0], acc[mt][nt][1]);
            *(float2*)(Cs + (size_t)(r0 + 8) * CSTR + c0) = make_float2(acc[mt][nt][2], acc[mt][nt][3]);
        }
    }
}

// ---------------- epilogue (R5-style full-row) -------------------------------
__device__ __forceinline__ void epi128(
    const float* Cs, char* Ahi, char* Alo, int tid, int row0, int M,
    const float* gvec, const float* bvec, const float* pre, const float* post,
    int relu, const float* wv, const float* wob, float* dot, float* outF, int writeA)
{
    if (tid >= 128) return;
    float v[128];
    const float4* cr = (const float4*)(Cs + (size_t)tid * CSTR);
    #pragma unroll
    for (int j = 0; j < 32; j++) {
        float4 a = cr[j];
        v[4*j] = a.x; v[4*j+1] = a.y; v[4*j+2] = a.z; v[4*j+3] = a.w;
    }
    const int grow = row0 + tid;
    const bool ok = grow < M;

    if (pre && ok) {
        const float4* q = (const float4*)(pre + (size_t)(grow / 6) * 128);
        #pragma unroll
        for (int j = 0; j < 32; j++) {
            float4 a = q[j];
            v[4*j] += a.x; v[4*j+1] += a.y; v[4*j+2] += a.z; v[4*j+3] += a.w;
        }
    }
    if (gvec) {
        float s = 0.f, q = 0.f;
        #pragma unroll
        for (int j = 0; j < 128; j++) { s += v[j]; q += v[j] * v[j]; }
        float m = s * (1.f / 128.f);
        float inv = rsqrtf(q * (1.f / 128.f) - m * m + EPS);
        #pragma unroll
        for (int j = 0; j < 128; j++) v[j] = (v[j] - m) * inv * gvec[j] + bvec[j];
    }
    if (post && ok) {
        const float4* q = (const float4*)(post + (size_t)grow * 128);
        #pragma unroll
        for (int j = 0; j < 32; j++) {
            float4 a = q[j];
            v[4*j] += a.x; v[4*j+1] += a.y; v[4*j+2] += a.z; v[4*j+3] += a.w;
        }
    }
    if (relu) {
        #pragma unroll
        for (int j = 0; j < 128; j++) v[j] = fmaxf(v[j], 0.f);
    }
    if (wv && ok) {
        float d = 0.f;
        #pragma unroll
        for (int j = 0; j < 128; j++) d += v[j] * wv[j];
        dot[grow] = d + wob[0];
    }
    if (outF && ok) {
        float4* dq = (float4*)(outF + (size_t)grow * 128);
        #pragma unroll
        for (int j = 0; j < 32; j++) dq[j] = make_float4(v[4*j], v[4*j+1], v[4*j+2], v[4*j+3]);
    }
    if (writeA) {
        char* hp = Ahi + tid * RS;
        char* lp = Alo + tid * RS;
        #pragma unroll
        for (int j = 0; j < 64; j++) {
            u32 p0 = packbf(v[2*j]), p1 = packbf(v[2*j+1]);
            *(u32*)(hp + j * 4) = (p0 >> 16) | (p1 & 0xffff0000u);
            *(u32*)(lp + j * 4) = (p0 & 0xffffu) | (p1 << 16);
        }
    }
}

// ---------------- K1: fused pred head (pW1 -> pW2 -> pWo) --------------------
__global__ void __launch_bounds__(256, 1) k_pred(
    const float* actors, const float* pg1, const float* pb1,
    const float* pg2, const float* pb2, const float* pbo, int N)
{
    extern __shared__ char smc[];
    float* gv0 = (float*)smc; float* bv0 = gv0 + 128;
    float* gv1 = bv0 + 128;   float* bv1 = gv1 + 128;
    float* bias = bv1 + 128;  // 64
    char* Ahi = smc + OF_AH; char* Alo = smc + OF_AL;
    char* Whi = smc + OF_WH; char* Wlo = smc + OF_WL;
    float* Cs = (float*)(smc + OF_WH);

    const int tid = threadIdx.x, wid = tid >> 5, lane = tid & 31;
    const int y = blockIdx.y, row0 = blockIdx.x * 128;
    const int wm = wid >> 2, wn = wid & 3, g = lane >> 2, tg = lane & 3;

    if (tid < 128) {
        gv0[tid] = pg1[y * 128 + tid]; bv0[tid] = pb1[y * 128 + tid];
        gv1[tid] = pg2[y * 128 + tid]; bv1[tid] = pb2[y * 128 + tid];
    }
    if (tid < 60) bias[tid] = pbo[y * 60 + tid];

    stageA(XP, Ahi, Alo, tid, row0, N);
    stageW128(WIMG + y * 16384, Whi, Wlo, tid);
    __syncthreads();

    float acc[4][4][4];
    // stage 0: h1 = relu(gn(actors @ pW1))
    mma_tile<4>(Ahi, Alo, Whi, Wlo, wm * 64, wn * 32, g, tg, acc);
    __syncthreads();
    store_C<4>(Cs, wm * 64, wn * 32, g, tg, acc);
    __syncthreads();
    epi128(Cs, Ahi, Alo, tid, row0, N, gv0, bv0, nullptr, nullptr, 1,
           nullptr, nullptr, nullptr, nullptr, 1);
    __syncthreads();

    // stage 1: h = relu(gn(h1 @ pW2) + actors)
    stageW128(WIMG + (6 + y) * 16384, Whi, Wlo, tid);
    __syncthreads();
    mma_tile<4>(Ahi, Alo, Whi, Wlo, wm * 64, wn * 32, g, tg, acc);
    __syncthreads();
    store_C<4>(Cs, wm * 64, wn * 32, g, tg, acc);
    __syncthreads();
    epi128(Cs, Ahi, Alo, tid, row0, N, gv1, bv1, nullptr, actors, 1,
           nullptr, nullptr, nullptr, nullptr, 1);
    __syncthreads();

    // stage 2: preds = h @ pWo + bias   (n = 64, cols 0..59 valid)
    stageW64(WOIMG + y * 8192, Whi, Wlo, tid);
    __syncthreads();
    float acc2[2][4][4];
    mma_tile<2>(Ahi, Alo, Whi, Wlo, (wid >> 1) * 32, (wid & 1) * 32, g, tg, acc2);
    __syncthreads();
    store_C<2>(Cs, (wid >> 1) * 32, (wid & 1) * 32, g, tg, acc2);
    __syncthreads();
    if (tid < 128) {
        int grow = row0 + tid;
        if (grow < N) {
            const float* cr = Cs + (size_t)tid * CSTR;
            float4* dst = (float4*)(S3 + (size_t)grow * 360 + y * 60);
            #pragma unroll
            for (int j = 0; j < 15; j++) {
                dst[j] = make_float4(cr[4*j] + bias[4*j],   cr[4*j+1] + bias[4*j+1],
                                     cr[4*j+2] + bias[4*j+2], cr[4*j+3] + bias[4*j+3]);
            }
        }
    }
}

// ---------------- K2: actB = actors @ agt_W[128:256] -------------------------
__global__ void __launch_bounds__(256, 1) k_actB(int N)
{
    extern __shared__ char smc[];
    char* Ahi = smc + OF_AH; char* Alo = smc + OF_AL;
    char* Whi = smc + OF_WH; char* Wlo = smc + OF_WL;
    float* Cs = (float*)(smc + OF_WH);

    const int tid = threadIdx.x, wid = tid >> 5, lane = tid & 31;
    const int row0 = blockIdx.x * 128;
    const int wm = wid >> 2, wn = wid & 3, g = lane >> 2, tg = lane & 3;

    stageA(XP, Ahi, Alo, tid, row0, N);
    stageW128(WIMG + 14 * 16384, Whi, Wlo, tid);
    __syncthreads();
    float acc[4][4][4];
    mma_tile<4>(Ahi, Alo, Whi, Wlo, wm * 64, wn * 32, g, tg, acc);
    __syncthreads();
    store_C<4>(Cs, wm * 64, wn * 32, g, tg, acc);
    __syncthreads();
    epi128(Cs, Ahi, Alo, tid, row0, N, nullptr, nullptr, nullptr, nullptr, 0,
           nullptr, nullptr, nullptr, S5, 0);
}

// ---------------- K3: fused chain (dist -> agt -> cls1 -> cls2) --------------
__global__ void __launch_bounds__(256, 1) k_chain(
    const float* dW0, const float* db0, const float* dg1, const float* db1v,
    const float* ag, const float* ab, const float* cg1, const float* cb1,
    const float* cg2, const float* cb2, const float* cWo, const float* cbo,
    float* feats, int M)
{
    extern __shared__ char smc[];
    float* base = (float*)smc;
    float* gvA = base;        float* bvA = base + 128;
    float* gvB = base + 256;  float* bvB = base + 384;
    float* gvC = base + 512;  float* bvC = base + 640;
    float* gvD = base + 768;  float* bvD = base + 896;
    float* wv  = base + 1024;
    float* w0a = base + 1152; float* w0b = base + 1280; float* b0v = base + 1408;
    float* pav = base + 1536; float* pbv = base + 1664;
    char* Ahi = smc + OF_AH; char* Alo = smc + OF_AL;
    char* Whi = smc + OF_WH; char* Wlo = smc + OF_WL;
    float* Cs = (float*)(smc + OF_WH);

    const int tid = threadIdx.x, wid = tid >> 5, lane = tid & 31;
    const int row0 = blockIdx.x * 128;
    const int wm = wid >> 2, wn = wid & 3, g = lane >> 2, tg = lane & 3;

    if (tid < 128) {
        gvA[tid] = dg1[tid]; bvA[tid] = db1v[tid];
        gvB[tid] = ag[tid];  bvB[tid] = ab[tid];
        gvC[tid] = cg1[tid]; bvC[tid] = cb1[tid];
        gvD[tid] = cg2[tid]; bvD[tid] = cb2[tid];
        wv[tid]  = cWo[tid];
        w0a[tid] = dW0[tid]; w0b[tid] = dW0[128 + tid]; b0v[tid] = db0[tid];
        int grow = row0 + tid; float a = 0.f, bq = 0.f;
        if (grow < M) { a = S3[(size_t)grow * 60 + 58]; bq = S3[(size_t)grow * 60 + 59]; }
        pav[tid] = a; pbv[tid] = bq;
    }
    stageW128(WIMG + 12 * 16384, Whi, Wlo, tid);
    __syncthreads();

    // gen A: relu(b0 - p58*W0[0] - p59*W0[1])
    #pragma unroll
    for (int it = 0; it < 32; it++) {
        int idx = tid + it * 256;
        int r = idx >> 6, k2 = (idx & 63) * 2;
        float x0 = fmaxf(b0v[k2]     - pav[r] * w0a[k2]     - pbv[r] * w0b[k2],     0.f);
        float x1 = fmaxf(b0v[k2 + 1] - pav[r] * w0a[k2 + 1] - pbv[r] * w0b[k2 + 1], 0.f);
        u32 p0 = packbf(x0), p1 = packbf(x1);
        int off = r * RS + k2 * 2;
        *(u32*)(Ahi + off) = (p0 >> 16) | (p1 & 0xffff0000u);
        *(u32*)(Alo + off) = (p0 & 0xffffu) | (p1 << 16);
    }
    __syncthreads();

    float acc[4][4][4];
    // stage 0: dh2 = relu(gn(dh @ dist_W1))
    mma_tile<4>(Ahi, Alo, Whi, Wlo, wm * 64, wn * 32, g, tg, acc);
    __syncthreads();
    store_C<4>(Cs, wm * 64, wn * 32, g, tg, acc);
    __syncthreads();
    epi128(Cs, Ahi, Alo, tid, row0, M, gvA, bvA, nullptr, nullptr, 1,
           nullptr, nullptr, nullptr, nullptr, 1);
    __syncthreads();

    // stage 1: feats = relu(gn(dh2 @ agt_W0 + actB))
    stageW128(WIMG + 13 * 16384, Whi, Wlo, tid);
    __syncthreads();
    mma_tile<4>(Ahi, Alo, Whi, Wlo, wm * 64, wn * 32, g, tg, acc);
    __syncthreads();
    store_C<4>(Cs, wm * 64, wn * 32, g, tg, acc);
    __syncthreads();
    epi128(Cs, Ahi, Alo, tid, row0, M, gvB, bvB, S5, nullptr, 1,
           nullptr, nullptr, nullptr, feats, 1);
    __syncthreads();

    // stage 2: c1 = relu(gn(feats @ cls_W1))
    stageW128(WIMG + 15 * 16384, Whi, Wlo, tid);
    __syncthreads();
    mma_tile<4>(Ahi, Alo, Whi, Wlo, wm * 64, wn * 32, g, tg, acc);
    __syncthreads();
    store_C<4>(Cs, wm * 64, wn * 32, g, tg, acc);
    __syncthreads();
    epi128(Cs, Ahi, Alo, tid, row0, M, gvC, bvC, nullptr, nullptr, 1,
           nullptr, nullptr, nullptr, nullptr, 1);
    __syncthreads();

    // stage 3: c = relu(gn(c1 @ cls_W2) + feats); logits = c @ cls_Wo + cbo
    stageW128(WIMG + 16 * 16384, Whi, Wlo, tid);
    __syncthreads();
    mma_tile<4>(Ahi, Alo, Whi, Wlo, wm * 64, wn * 32, g, tg, acc);
    __syncthreads();
    store_C<4>(Cs, wm * 64, wn * 32, g, tg, acc);
    __syncthreads();
    epi128(Cs, Ahi, Alo, tid, row0, M, gvD, bvD, nullptr, feats, 1,
           wv, cbo, S4, nullptr, 0);
}

// ---------------- softmax + rank-sort + reg gather ---------------------------
__global__ void finalize(const float* ctr, float* clsO, float* regO, int N)
{
    int w = (blockIdx.x * blockDim.x + threadIdx.x) >> 5;
    int lane = threadIdx.x & 31;
    if (w >= N) return;
    float v = (lane < 6) ? S4[(size_t)w * 6 + lane] : -3.4e38f;
    float m = v;
    #pragma unroll
    for (int s = 4; s >= 1; s >>= 1) m = fmaxf(m, __shfl_xor_sync(~0u, m, s));
    float e = (lane < 6) ? expf(v - m) : 0.f;
    float s = e;
    #pragma unroll
    for (int t = 4; t >= 1; t >>= 1) s += __shfl_xor_sync(~0u, s, t);
    float pr = e / s;
    int rk = 0;
    #pragma unroll
    for (int j = 0; j < 6; j++) {
        float pj = __shfl_sync(~0u, pr, j);
        rk += (pj > pr) || (pj == pr && j < lane);
    }
    if (lane < 6) clsO[(size_t)w * 6 + rk] = pr;
    float cx = ctr[(size_t)w * 2], cy = ctr[(size_t)w * 2 + 1];
    for (int k = 0; k < 6; k++) {
        int r = __shfl_sync(~0u, rk, k);
        const float* sp = S3 + (size_t)w * 360 + k * 60;
        float* dp = regO + ((size_t)w * 6 + r) * 60;
        for (int j = lane; j < 60; j += 32) dp[j] = sp[j] + ((j & 1) ? cy : cx);
    }
}

// ---------------- host orchestration ----------------------------------------
extern "C" void kernel_launch(void* const* d_in, const int* in_sizes, int n_in,
                              void* d_out, int out_size)
{
    const float* actors = (const float*)d_in[0];
    const float* ctrs   = (const float*)d_in[1];
    const float* pW1 = (const float*)d_in[2];
    const float* pg1 = (const float*)d_in[3];
    const float* pb1 = (const float*)d_in[4];
    const float* pW2 = (const float*)d_in[5];
    const float* pg2 = (const float*)d_in[6];
    const float* pb2 = (const float*)d_in[7];
    const float* pWo = (const float*)d_in[8];
    const float* pbo = (const float*)d_in[9];
    const float* dW0 = (const float*)d_in[10];
    const float* db0 = (const float*)d_in[11];
    const float* dW1 = (const float*)d_in[12];
    const float* dg1 = (const float*)d_in[13];
    const float* db1 = (const float*)d_in[14];
    const float* aW  = (const float*)d_in[15];
    const float* ag  = (const float*)d_in[16];
    const float* ab  = (const float*)d_in[17];
    const float* cW1 = (const float*)d_in[18];
    const float* cg1 = (const float*)d_in[19];
    const float* cb1 = (const float*)d_in[20];
    const float* cW2 = (const float*)d_in[21];
    const float* cg2 = (const float*)d_in[22];
    const float* cb2 = (const float*)d_in[23];
    const float* cWo = (const float*)d_in[24];
    const float* cbo = (const float*)d_in[25];

    const int N = in_sizes[0] / 128;       // 100000
    const int M = N * 6;
    const int gN = (N + 127) / 128, gM = (M + 127) / 128;
    float* out   = (float*)d_out;
    float* regO  = out + (size_t)N * 6;
    float* feats = regO + (size_t)N * 360;

    cudaFuncSetAttribute(k_pred,  cudaFuncAttributeMaxDynamicSharedMemorySize, SMEMB);
    cudaFuncSetAttribute(k_actB,  cudaFuncAttributeMaxDynamicSharedMemorySize, SMEMB);
    cudaFuncSetAttribute(k_chain, cudaFuncAttributeMaxDynamicSharedMemorySize, SMEMB);

    prep_w<<<17, 128>>>(pW1, pW2, dW1, aW, cW1, cW2);
    prep_wo<<<6, 128>>>(pWo);
    prep_x<<<(N * 128 + 255) / 256, 256>>>(actors, N * 128);

    k_pred<<<dim3(gN, 6), 256, SMEMB>>>(actors, pg1, pb1, pg2, pb2, pbo, N);
    k_actB<<<gN, 256, SMEMB>>>(N);
    k_chain<<<gM, 256, SMEMB>>>(dW0, db0, dg1, db1, ag, ab, cg1, cb1,
                                cg2, cb2, cWo, cbo, feats, M);
    finalize<<<(N + 7) / 8, 256>>>(ctrs, out, regO, N);
}

// round 13
// speedup vs baseline: 2.3945x; 1.5715x over previous
#include <cuda_runtime.h>
#include <cuda_bf16.h>
#include <cstdint>

typedef unsigned long long u64;
typedef long long i64;
typedef uint32_t u32;

#define EPS 1e-5f
#define RS  272                      // A plane row stride (bytes): 68 u32 ≡ 4 mod 32
#define WRS 144                      // W half-plane row stride (bytes): 36 u32 ≡ 4 mod 32
#define VEC 8704
#define OF_AH VEC                    // A hi plane  (128 x 272 = 34816)
#define OF_AL (OF_AH + 34816)
#define OF_WH (OF_AL + 34816)        // W hi half-plane (128 x 144 = 18432)
#define OF_WL (OF_WH + 18432)
#define SMEMB (OF_WL + 18432)        // 115200 -> 2 CTAs/SM

// ---------------- scratch (device globals; no runtime alloc) ----------------
__device__ __align__(16) u32   XP[100000u * 128];   // actors packed
__device__ __align__(16) u32   WIMG[17 * 16384];    // packed W [n][k]
__device__ __align__(16) u32   WOIMG[6 * 8192];     // packed Wo [o(64)][k]
__device__ __align__(16) float S3[600000u * 60];    // preds [(n*6+k)][60]
__device__ __align__(16) float S4[600000];          // cls logits
__device__ __align__(16) float S5[100000u * 128];   // actB fp32

// ---------------- helpers ----------------------------------------------------
__device__ __forceinline__ u32 packbf(float x) {
    u32 hb = (u32)__bfloat16_as_ushort(__float2bfloat16(x));
    float r = x - __uint_as_float(hb << 16);
    return (hb << 16) | (u32)__bfloat16_as_ushort(__float2bfloat16(r));
}
__device__ __forceinline__ void mma16816(float* c, const u32* a, const u32* b) {
    asm volatile(
        "mma.sync.aligned.m16n8k16.row.col.f32.bf16.bf16.f32 "
        "{%0,%1,%2,%3}, {%4,%5,%6,%7}, {%8,%9}, {%0,%1,%2,%3};"
        : "+f"(c[0]), "+f"(c[1]), "+f"(c[2]), "+f"(c[3])
        : "r"(a[0]), "r"(a[1]), "r"(a[2]), "r"(a[3]), "r"(b[0]), "r"(b[1]));
}
__device__ __forceinline__ u32 bph(u32 x, u32 y) { return __byte_perm(x, y, 0x7632); }
__device__ __forceinline__ u32 bpl(u32 x, u32 y) { return __byte_perm(x, y, 0x5410); }

// ---------------- prep kernels ----------------------------------------------
__global__ void prep_w(const float* pW1, const float* pW2, const float* dW1,
                       const float* aW, const float* cW1, const float* cW2)
{
    int id = blockIdx.x;
    const float* W;
    if      (id < 6)   W = pW1 + id * 16384;
    else if (id < 12)  W = pW2 + (id - 6) * 16384;
    else if (id == 12) W = dW1;
    else if (id == 13) W = aW;
    else if (id == 14) W = aW + 16384;
    else if (id == 15) W = cW1;
    else               W = cW2;
    u32* dst = WIMG + id * 16384;
    for (int idx = threadIdx.x; idx < 16384; idx += blockDim.x) {
        int n = idx >> 7, k = idx & 127;
        dst[idx] = packbf(W[k * 128 + n]);
    }
}
__global__ void prep_wo(const float* pWo) {
    int y = blockIdx.x;
    u32* dst = WOIMG + y * 8192;
    for (int idx = threadIdx.x; idx < 8192; idx += blockDim.x) {
        int o = idx >> 7, k = idx & 127;
        float x = (o < 60) ? pWo[y * 7680 + k * 60 + o] : 0.f;
        dst[idx] = packbf(x);
    }
}
__global__ void prep_x(const float* a, int n) {
    int i = blockIdx.x * blockDim.x + threadIdx.x;
    if (i < n) XP[i] = packbf(a[i]);
}

// ---------------- staging ----------------------------------------------------
__device__ __forceinline__ void stageA(const u32* Ag, char* hi, char* lo, int tid, int row0, int M) {
    #pragma unroll
    for (int i = 0; i < 16; i++) {
        int idx = tid + 256 * i;
        int r = idx >> 5, c4 = (idx & 31) * 4;
        int gr = row0 + r;
        uint4 v = make_uint4(0u, 0u, 0u, 0u);
        if (gr < M) v = ((const uint4*)(Ag + (size_t)gr * 128))[idx & 31];
        int off = r * RS + c4 * 2;
        *(uint2*)(hi + off) = make_uint2(bph(v.x, v.y), bph(v.z, v.w));
        *(uint2*)(lo + off) = make_uint2(bpl(v.x, v.y), bpl(v.z, v.w));
    }
}
template <int NR>
__device__ __forceinline__ void stageWhalf(const u32* src, int k0, char* hi, char* lo, int tid) {
    #pragma unroll
    for (int i = 0; i < NR / 16; i++) {        // NR*16/256
        int idx = tid + 256 * i;
        int r = idx >> 4, c4 = (idx & 15) * 4;
        uint4 v = *(const uint4*)(src + r * 128 + k0 + c4);
        int off = r * WRS + c4 * 2;
        *(uint2*)(hi + off) = make_uint2(bph(v.x, v.y), bph(v.z, v.w));
        *(uint2*)(lo + off) = make_uint2(bpl(v.x, v.y), bpl(v.z, v.w));
    }
}

// ---------------- MMA over one W k-half --------------------------------------
template <int MT>
__device__ __forceinline__ void mma_half(const char* smc, int rbase, int nbase,
                                         int g, int tg, int ks0, float (&acc)[MT][4][4])
{
    const char* Ahi = smc + OF_AH; const char* Alo = smc + OF_AL;
    const char* Wh  = smc + OF_WH; const char* Wl  = smc + OF_WL;
    #pragma unroll
    for (int kh = 0; kh < 4; kh++) {
        const int cA = ((ks0 + kh) * 16 + tg * 2) * 2;
        const int cW = (kh * 16 + tg * 2) * 2;
        u32 bh[4][2], bl[4][2];
        #pragma unroll
        for (int nt = 0; nt < 4; nt++) {
            int nb = (nbase + nt * 8 + g) * WRS;
            bh[nt][0] = *(const u32*)(Wh + nb + cW);
            bh[nt][1] = *(const u32*)(Wh + nb + cW + 16);
            bl[nt][0] = *(const u32*)(Wl + nb + cW);
            bl[nt][1] = *(const u32*)(Wl + nb + cW + 16);
        }
        #pragma unroll
        for (int mt = 0; mt < MT; mt++) {
            int rb = (rbase + mt * 16 + g) * RS;
            u32 ah[4] = { *(const u32*)(Ahi + rb + cA), *(const u32*)(Ahi + rb + 8 * RS + cA),
                          *(const u32*)(Ahi + rb + cA + 16), *(const u32*)(Ahi + rb + 8 * RS + cA + 16) };
            u32 al[4] = { *(const u32*)(Alo + rb + cA), *(const u32*)(Alo + rb + 8 * RS + cA),
                          *(const u32*)(Alo + rb + cA + 16), *(const u32*)(Alo + rb + 8 * RS + cA + 16) };
            #pragma unroll
            for (int nt = 0; nt < 4; nt++) {
                mma16816(acc[mt][nt], ah, bh[nt]);
                mma16816(acc[mt][nt], al, bh[nt]);
                mma16816(acc[mt][nt], ah, bl[nt]);
            }
        }
    }
}

// ---------------- accumulator epilogue (GN/res/relu/dot/writes) --------------
// NOTE: any stage with writeA=1 must have gb4 != null (its sync orders A reuse).
__device__ __forceinline__ void epi_main(
    char* smc, float (&acc)[4][4][4],
    int wm, int wn, int g, int tg, int row0, int M,
    const float4* gb4, const float* pre, const float* post, int relu,
    const float2* wv2, const float* wob, float* dot,
    float* outF, int writeA)
{
    float2* sred = (float2*)(smc + 4608);
    const int cbase = wn * 32 + tg * 2;
    const int rloc0 = wm * 64 + g;

    if (pre) {
        #pragma unroll
        for (int mt = 0; mt < 4; mt++)
        #pragma unroll
        for (int h = 0; h < 2; h++) {
            int R = row0 + rloc0 + mt * 16 + 8 * h;
            if (R < M) {
                const float* pr = pre + (size_t)(R / 6) * 128;
                #pragma unroll
                for (int nt = 0; nt < 4; nt++) {
                    float2 a = *(const float2*)(pr + cbase + nt * 8);
                    acc[mt][nt][2*h] += a.x; acc[mt][nt][2*h+1] += a.y;
                }
            }
        }
    }
    if (gb4) {
        #pragma unroll
        for (int mt = 0; mt < 4; mt++)
        #pragma unroll
        for (int h = 0; h < 2; h++) {
            float s = 0.f, ss = 0.f;
            #pragma unroll
            for (int nt = 0; nt < 4; nt++) {
                float x = acc[mt][nt][2*h], yv = acc[mt][nt][2*h+1];
                s += x + yv; ss += x * x + yv * yv;
            }
            s += __shfl_xor_sync(~0u, s, 1); ss += __shfl_xor_sync(~0u, ss, 1);
            s += __shfl_xor_sync(~0u, s, 2); ss += __shfl_xor_sync(~0u, ss, 2);
            if (tg == 0) sred[(rloc0 + mt * 16 + 8 * h) * 4 + wn] = make_float2(s, ss);
        }
        __syncthreads();
        float mv[4][2], iv[4][2];
        #pragma unroll
        for (int mt = 0; mt < 4; mt++)
        #pragma unroll
        for (int h = 0; h < 2; h++) {
            int rl = (rloc0 + mt * 16 + 8 * h) * 4;
            float2 t0 = sred[rl], t1 = sred[rl+1], t2 = sred[rl+2], t3 = sred[rl+3];
            float s = t0.x + t1.x + t2.x + t3.x, ss = t0.y + t1.y + t2.y + t3.y;
            float m = s * (1.f / 128.f);
            mv[mt][h] = m;
            iv[mt][h] = rsqrtf(ss * (1.f / 128.f) - m * m + EPS);
        }
        #pragma unroll
        for (int nt = 0; nt < 4; nt++) {
            float4 q = gb4[(cbase + nt * 8) >> 1];
            #pragma unroll
            for (int mt = 0; mt < 4; mt++)
            #pragma unroll
            for (int h = 0; h < 2; h++) {
                acc[mt][nt][2*h]   = (acc[mt][nt][2*h]   - mv[mt][h]) * iv[mt][h] * q.x + q.y;
                acc[mt][nt][2*h+1] = (acc[mt][nt][2*h+1] - mv[mt][h]) * iv[mt][h] * q.z + q.w;
            }
        }
    }
    if (post) {
        #pragma unroll
        for (int mt = 0; mt < 4; mt++)
        #pragma unroll
        for (int h = 0; h < 2; h++) {
            int R = row0 + rloc0 + mt * 16 + 8 * h;
            if (R < M) {
                const float* pr = post + (size_t)R * 128;
                #pragma unroll
                for (int nt = 0; nt < 4; nt++) {
                    float2 a = *(const float2*)(pr + cbase + nt * 8);
                    acc[mt][nt][2*h] += a.x; acc[mt][nt][2*h+1] += a.y;
                }
            }
        }
    }
    if (relu) {
        #pragma unroll
        for (int mt = 0; mt < 4; mt++)
        #pragma unroll
        for (int nt = 0; nt < 4; nt++)
        #pragma unroll
        for (int q = 0; q < 4; q++) acc[mt][nt][q] = fmaxf(acc[mt][nt][q], 0.f);
    }
    if (wv2) {
        __syncthreads();             // GN sred reads done before reuse
        #pragma unroll
        for (int mt = 0; mt < 4; mt++)
        #pragma unroll
        for (int h = 0; h < 2; h++) {
            float d = 0.f;
            #pragma unroll
            for (int nt = 0; nt < 4; nt++) {
                float2 w = wv2[(cbase + nt * 8) >> 1];
                d += acc[mt][nt][2*h] * w.x + acc[mt][nt][2*h+1] * w.y;
            }
            d += __shfl_xor_sync(~0u, d, 1);
            d += __shfl_xor_sync(~0u, d, 2);
            if (tg == 0) sred[(rloc0 + mt * 16 + 8 * h) * 4 + wn].x = d;
        }
        __syncthreads();
        if (wn == 0 && tg == 0) {
            #pragma unroll
            for (int mt = 0; mt < 4; mt++)
            #pragma unroll
            for (int h = 0; h < 2; h++) {
                int rl = (rloc0 + mt * 16 + 8 * h) * 4;
                float t = sred[rl].x + sred[rl+1].x + sred[rl+2].x + sred[rl+3].x;
                int R = row0 + rloc0 + mt * 16 + 8 * h;
                if (R < M) dot[R] = t + wob[0];
            }
        }
    }
    if (outF) {
        #pragma unroll
        for (int mt = 0; mt < 4; mt++)
        #pragma unroll
        for (int h = 0; h < 2; h++) {
            int R = row0 + rloc0 + mt * 16 + 8 * h;
            if (R < M) {
                float* o = outF + (size_t)R * 128;
                #pragma unroll
                for (int nt = 0; nt < 4; nt++)
                    *(float2*)(o + cbase + nt * 8) = make_float2(acc[mt][nt][2*h], acc[mt][nt][2*h+1]);
            }
        }
    }
    if (writeA) {
        char* Ahi = smc + OF_AH; char* Alo = smc + OF_AL;
        #pragma unroll
        for (int mt = 0; mt < 4; mt++)
        #pragma unroll
        for (int h = 0; h < 2; h++) {
            int rl = rloc0 + mt * 16 + 8 * h;
            char* hp = Ahi + rl * RS;
            char* lp = Alo + rl * RS;
            #pragma unroll
            for (int nt = 0; nt < 4; nt++) {
                int c = cbase + nt * 8;
                u32 p0 = packbf(acc[mt][nt][2*h]), p1 = packbf(acc[mt][nt][2*h+1]);
                *(u32*)(hp + c * 2) = (p0 >> 16) | (p1 & 0xffff0000u);
                *(u32*)(lp + c * 2) = (p0 & 0xffffu) | (p1 << 16);
            }
        }
    }
}

// ---------------- one fused 128x128 stage ------------------------------------
__device__ __forceinline__ void stage128(
    char* smc, const u32* Wsrc, int tid, int row0, int M,
    const float4* gb4, const float* pre, const float* post, int relu,
    const float2* wv2, const float* wob, float* dot, float* outF, int writeA)
{
    const int wid = tid >> 5, lane = tid & 31;
    const int wm = wid >> 2, wn = wid & 3, g = lane >> 2, tg = lane & 3;
    float acc[4][4][4];
    #pragma unroll
    for (int i = 0; i < 4; i++)
        #pragma unroll
        for (int j = 0; j < 4; j++)
            #pragma unroll
            for (int q = 0; q < 4; q++) acc[i][j][q] = 0.f;

    stageWhalf<128>(Wsrc, 0, smc + OF_WH, smc + OF_WL, tid);
    __syncthreads();
    mma_half<4>(smc, wm * 64, wn * 32, g, tg, 0, acc);
    __syncthreads();
    stageWhalf<128>(Wsrc, 64, smc + OF_WH, smc + OF_WL, tid);
    __syncthreads();
    mma_half<4>(smc, wm * 64, wn * 32, g, tg, 4, acc);
    epi_main(smc, acc, wm, wn, g, tg, row0, M, gb4, pre, post, relu, wv2, wob, dot, outF, writeA);
    __syncthreads();
}

// ---------------- K1: fused pred head ----------------------------------------
__global__ void __launch_bounds__(256, 2) k_pred(
    const float* actors, const float* pg1, const float* pb1,
    const float* pg2, const float* pb2, const float* pbo, int N)
{
    extern __shared__ char smc[];
    float4* gb0 = (float4*)smc;
    float4* gb1 = (float4*)(smc + 1024);
    float2* bias2 = (float2*)(smc + 4096);
    const int tid = threadIdx.x;
    const int y = blockIdx.y, row0 = blockIdx.x * 128;

    if (tid < 64) {
        int c = 2 * tid;
        gb0[tid] = make_float4(pg1[y*128+c], pb1[y*128+c], pg1[y*128+c+1], pb1[y*128+c+1]);
        gb1[tid] = make_float4(pg2[y*128+c], pb2[y*128+c], pg2[y*128+c+1], pb2[y*128+c+1]);
    }
    if (tid < 32) {
        int c = 2 * tid;
        bias2[tid] = make_float2(c < 60 ? pbo[y*60+c] : 0.f, c+1 < 60 ? pbo[y*60+c+1] : 0.f);
    }
    stageA(XP, smc + OF_AH, smc + OF_AL, tid, row0, N);

    stage128(smc, WIMG + y * 16384, tid, row0, N, gb0, nullptr, nullptr, 1,
             nullptr, nullptr, nullptr, nullptr, 1);
    stage128(smc, WIMG + (6 + y) * 16384, tid, row0, N, gb1, nullptr, actors, 1,
             nullptr, nullptr, nullptr, nullptr, 1);

    // stage 2: preds = h @ Wo + bias (n=64, cols 0..59)
    {
        const int wid = tid >> 5, lane = tid & 31;
        const int g = lane >> 2, tg = lane & 3;
        const int rbase = (wid >> 1) * 32, nbase = (wid & 1) * 32;
        float acc[2][4][4];
        #pragma unroll
        for (int i = 0; i < 2; i++)
            #pragma unroll
            for (int j = 0; j < 4; j++)
                #pragma unroll
                for (int q = 0; q < 4; q++) acc[i][j][q] = 0.f;
        stageWhalf<64>(WOIMG + y * 8192, 0, smc + OF_WH, smc + OF_WL, tid);
        __syncthreads();
        mma_half<2>(smc, rbase, nbase, g, tg, 0, acc);
        __syncthreads();
        stageWhalf<64>(WOIMG + y * 8192, 64, smc + OF_WH, smc + OF_WL, tid);
        __syncthreads();
        mma_half<2>(smc, rbase, nbase, g, tg, 4, acc);
        #pragma unroll
        for (int mt = 0; mt < 2; mt++)
        #pragma unroll
        for (int h = 0; h < 2; h++) {
            int R = row0 + rbase + mt * 16 + g + 8 * h;
            if (R < N) {
                float* o = S3 + (size_t)R * 360 + y * 60;
                #pragma unroll
                for (int nt = 0; nt < 4; nt++) {
                    int c = nbase + nt * 8 + tg * 2;
                    if (c < 60) {
                        float2 bb = bias2[c >> 1];
                        o[c]     = acc[mt][nt][2*h]   + bb.x;
                        o[c + 1] = acc[mt][nt][2*h+1] + bb.y;
                    }
                }
            }
        }
    }
}

// ---------------- K2: actB = actors @ agt_W[128:256] -------------------------
__global__ void __launch_bounds__(256, 2) k_actB(int N)
{
    extern __shared__ char smc[];
    const int tid = threadIdx.x;
    const int row0 = blockIdx.x * 128;
    const int wid = tid >> 5, lane = tid & 31;
    const int wm = wid >> 2, wn = wid & 3, g = lane >> 2, tg = lane & 3;

    stageA(XP, smc + OF_AH, smc + OF_AL, tid, row0, N);
    float acc[4][4][4];
    #pragma unroll
    for (int i = 0; i < 4; i++)
        #pragma unroll
        for (int j = 0; j < 4; j++)
            #pragma unroll
            for (int q = 0; q < 4; q++) acc[i][j][q] = 0.f;
    stageWhalf<128>(WIMG + 14 * 16384, 0, smc + OF_WH, smc + OF_WL, tid);
    __syncthreads();
    mma_half<4>(smc, wm * 64, wn * 32, g, tg, 0, acc);
    __syncthreads();
    stageWhalf<128>(WIMG + 14 * 16384, 64, smc + OF_WH, smc + OF_WL, tid);
    __syncthreads();
    mma_half<4>(smc, wm * 64, wn * 32, g, tg, 4, acc);
    #pragma unroll
    for (int mt = 0; mt < 4; mt++)
    #pragma unroll
    for (int h = 0; h < 2; h++) {
        int R = row0 + wm * 64 + mt * 16 + g + 8 * h;
        if (R < N) {
            float* o = S5 + (size_t)R * 128;
            #pragma unroll
            for (int nt = 0; nt < 4; nt++)
                *(float2*)(o + wn * 32 + nt * 8 + tg * 2) =
                    make_float2(acc[mt][nt][2*h], acc[mt][nt][2*h+1]);
        }
    }
}

// ---------------- K3: fused chain (dist -> agt -> cls1 -> cls2) --------------
__global__ void __launch_bounds__(256, 2) k_chain(
    const float* dW0, const float* db0, const float* dg1, const float* db1v,
    const float* ag, const float* ab, const float* cg1, const float* cb1,
    const float* cg2, const float* cb2, const float* cWo, const float* cbo,
    float* feats, int M)
{
    extern __shared__ char smc[];
    float4* gbA = (float4*)smc;
    float4* gbB = (float4*)(smc + 1024);
    float4* gbC = (float4*)(smc + 2048);
    float4* gbD = (float4*)(smc + 3072);
    float2* wv2 = (float2*)(smc + 4096);
    float* w0a = (float*)(smc + 4608);
    float* w0b = (float*)(smc + 5120);
    float* b0v = (float*)(smc + 5632);
    float* pav = (float*)(smc + 6144);
    float* pbv = (float*)(smc + 6656);
    char* Ahi = smc + OF_AH; char* Alo = smc + OF_AL;

    const int tid = threadIdx.x;
    const int row0 = blockIdx.x * 128;

    if (tid < 64) {
        int c = 2 * tid;
        gbA[tid] = make_float4(dg1[c], db1v[c], dg1[c+1], db1v[c+1]);
        gbB[tid] = make_float4(ag[c],  ab[c],   ag[c+1],  ab[c+1]);
        gbC[tid] = make_float4(cg1[c], cb1[c],  cg1[c+1], cb1[c+1]);
        gbD[tid] = make_float4(cg2[c], cb2[c],  cg2[c+1], cb2[c+1]);
        wv2[tid] = make_float2(cWo[c], cWo[c+1]);
    }
    if (tid < 128) {
        w0a[tid] = dW0[tid]; w0b[tid] = dW0[128 + tid]; b0v[tid] = db0[tid];
        int R = row0 + tid; float a = 0.f, bq = 0.f;
        if (R < M) { a = S3[(size_t)R * 60 + 58]; bq = S3[(size_t)R * 60 + 59]; }
        pav[tid] = a; pbv[tid] = bq;
    }
    __syncthreads();

    // generate dist A: relu(b0 - p58*W0[0] - p59*W0[1])
    #pragma unroll
    for (int it = 0; it < 32; it++) {
        int idx = tid + it * 256;
        int r = idx >> 6, k2 = (idx & 63) * 2;
        float x0 = fmaxf(b0v[k2]     - pav[r] * w0a[k2]     - pbv[r] * w0b[k2],     0.f);
        float x1 = fmaxf(b0v[k2 + 1] - pav[r] * w0a[k2 + 1] - pbv[r] * w0b[k2 + 1], 0.f);
        u32 p0 = packbf(x0), p1 = packbf(x1);
        int off = r * RS + k2 * 2;
        *(u32*)(Ahi + off) = (p0 >> 16) | (p1 & 0xffff0000u);
        *(u32*)(Alo + off) = (p0 & 0xffffu) | (p1 << 16);
    }

    stage128(smc, WIMG + 12 * 16384, tid, row0, M, gbA, nullptr, nullptr, 1,
             nullptr, nullptr, nullptr, nullptr, 1);
    stage128(smc, WIMG + 13 * 16384, tid, row0, M, gbB, S5, nullptr, 1,
             nullptr, nullptr, nullptr, feats, 1);
    stage128(smc, WIMG + 15 * 16384, tid, row0, M, gbC, nullptr, nullptr, 1,
             nullptr, nullptr, nullptr, nullptr, 1);
    stage128(smc, WIMG + 16 * 16384, tid, row0, M, gbD, nullptr, feats, 1,
             wv2, cbo, S4, nullptr, 0);
}

// ---------------- softmax + rank-sort + reg gather ---------------------------
__global__ void finalize(const float* ctr, float* clsO, float* regO, int N)
{
    int w = (blockIdx.x * blockDim.x + threadIdx.x) >> 5;
    int lane = threadIdx.x & 31;
    if (w >= N) return;
    float v = (lane < 6) ? S4[(size_t)w * 6 + lane] : -3.4e38f;
    float m = v;
    #pragma unroll
    for (int s = 4; s >= 1; s >>= 1) m = fmaxf(m, __shfl_xor_sync(~0u, m, s));
    float e = (lane < 6) ? expf(v - m) : 0.f;
    float s = e;
    #pragma unroll
    for (int t = 4; t >= 1; t >>= 1) s += __shfl_xor_sync(~0u, s, t);
    float pr = e / s;
    int rk = 0;
    #pragma unroll
    for (int j = 0; j < 6; j++) {
        float pj = __shfl_sync(~0u, pr, j);
        rk += (pj > pr) || (pj == pr && j < lane);
    }
    if (lane < 6) clsO[(size_t)w * 6 + rk] = pr;
    float cx = ctr[(size_t)w * 2], cy = ctr[(size_t)w * 2 + 1];
    for (int k = 0; k < 6; k++) {
        int r = __shfl_sync(~0u, rk, k);
        const float* sp = S3 + (size_t)w * 360 + k * 60;
        float* dp = regO + ((size_t)w * 6 + r) * 60;
        for (int j = lane; j < 60; j += 32) dp[j] = sp[j] + ((j & 1) ? cy : cx);
    }
}

// ---------------- host orchestration ----------------------------------------
extern "C" void kernel_launch(void* const* d_in, const int* in_sizes, int n_in,
                              void* d_out, int out_size)
{
    const float* actors = (const float*)d_in[0];
    const float* ctrs   = (const float*)d_in[1];
    const float* pW1 = (const float*)d_in[2];
    const float* pg1 = (const float*)d_in[3];
    const float* pb1 = (const float*)d_in[4];
    const float* pW2 = (const float*)d_in[5];
    const float* pg2 = (const float*)d_in[6];
    const float* pb2 = (const float*)d_in[7];
    const float* pWo = (const float*)d_in[8];
    const float* pbo = (const float*)d_in[9];
    const float* dW0 = (const float*)d_in[10];
    const float* db0 = (const float*)d_in[11];
    const float* dW1 = (const float*)d_in[12];
    const float* dg1 = (const float*)d_in[13];
    const float* db1 = (const float*)d_in[14];
    const float* aW  = (const float*)d_in[15];
    const float* ag  = (const float*)d_in[16];
    const float* ab  = (const float*)d_in[17];
    const float* cW1 = (const float*)d_in[18];
    const float* cg1 = (const float*)d_in[19];
    const float* cb1 = (const float*)d_in[20];
    const float* cW2 = (const float*)d_in[21];
    const float* cg2 = (const float*)d_in[22];
    const float* cb2 = (const float*)d_in[23];
    const float* cWo = (const float*)d_in[24];
    const float* cbo = (const float*)d_in[25];

    const int N = in_sizes[0] / 128;       // 100000
    const int M = N * 6;
    const int gN = (N + 127) / 128, gM = (M + 127) / 128;
    float* out   = (float*)d_out;
    float* regO  = out + (size_t)N * 6;
    float* feats = regO + (size_t)N * 360;

    cudaFuncSetAttribute(k_pred,  cudaFuncAttributeMaxDynamicSharedMemorySize, SMEMB);
    cudaFuncSetAttribute(k_actB,  cudaFuncAttributeMaxDynamicSharedMemorySize, SMEMB);
    cudaFuncSetAttribute(k_chain, cudaFuncAttributeMaxDynamicSharedMemorySize, SMEMB);

    prep_w<<<17, 128>>>(pW1, pW2, dW1, aW, cW1, cW2);
    prep_wo<<<6, 128>>>(pWo);
    prep_x<<<(N * 128 + 255) / 256, 256>>>(actors, N * 128);

    k_pred<<<dim3(gN, 6), 256, SMEMB>>>(actors, pg1, pb1, pg2, pb2, pbo, N);
    k_actB<<<gN, 256, SMEMB>>>(N);
    k_chain<<<gM, 256, SMEMB>>>(dW0, db0, dg1, db1, ag, ab, cg1, cb1,
                                cg2, cb2, cWo, cbo, feats, M);
    finalize<<<(N + 7) / 8, 256>>>(ctrs, out, regO, N);
}

// round 14
// speedup vs baseline: 2.4400x; 1.0190x over previous
#include <cuda_runtime.h>
#include <cuda_bf16.h>
#include <cstdint>

typedef unsigned long long u64;
typedef long long i64;
typedef uint32_t u32;

#define EPS 1e-5f
#define RS  272                      // A plane row stride (bytes): 68 u32 ≡ 4 mod 32
#define WRS 144                      // W half-plane row stride (bytes): 36 u32 ≡ 4 mod 32
#define VEC 8704
#define OF_AH VEC                    // A hi plane  (128 x 272 = 34816)
#define OF_AL (OF_AH + 34816)
#define OF_WH (OF_AL + 34816)        // W hi half-plane (128 x 144 = 18432)
#define OF_WL (OF_WH + 18432)
#define SMEMB (OF_WL + 18432)        // 115200 -> 2 CTAs/SM

// ---------------- scratch (device globals; no runtime alloc) ----------------
__device__ __align__(16) __nv_bfloat16 XPH[100000u * 128];  // actors hi plane
__device__ __align__(16) __nv_bfloat16 XPL[100000u * 128];  // actors lo plane
__device__ __align__(16) __nv_bfloat16 WSP[17 * 32768];     // W: [id][plane][n][k]
__device__ __align__(16) __nv_bfloat16 WOSP[6 * 32768];     // Wo: [y][plane][o(128)][k]
__device__ __align__(16) float S3[600000u * 60];            // preds
__device__ __align__(16) float S4[600000];                  // cls logits
__device__ __align__(16) float S5[100000u * 128];           // actB fp32

// ---------------- helpers ----------------------------------------------------
__device__ __forceinline__ u32 packbf(float x) {
    u32 hb = (u32)__bfloat16_as_ushort(__float2bfloat16(x));
    float r = x - __uint_as_float(hb << 16);
    return (hb << 16) | (u32)__bfloat16_as_ushort(__float2bfloat16(r));
}
__device__ __forceinline__ void mma16816(float* c, const u32* a, const u32* b) {
    asm volatile(
        "mma.sync.aligned.m16n8k16.row.col.f32.bf16.bf16.f32 "
        "{%0,%1,%2,%3}, {%4,%5,%6,%7}, {%8,%9}, {%0,%1,%2,%3};"
        : "+f"(c[0]), "+f"(c[1]), "+f"(c[2]), "+f"(c[3])
        : "r"(a[0]), "r"(a[1]), "r"(a[2]), "r"(a[3]), "r"(b[0]), "r"(b[1]));
}
__device__ __forceinline__ u32 smem_u32p(const void* p) {
    u32 a;
    asm("{ .reg .u64 t; cvta.to.shared.u64 t, %1; cvt.u32.u64 %0, t; }" : "=r"(a) : "l"(p));
    return a;
}
__device__ __forceinline__ void cpa16(u32 dst, const void* src, int sz) {
    asm volatile("cp.async.ca.shared.global [%0], [%1], 16, %2;"
                 :: "r"(dst), "l"(src), "r"(sz) : "memory");
}
#define CPA_COMMIT() asm volatile("cp.async.commit_group;" ::: "memory")
#define CPA_WAIT0()  asm volatile("cp.async.wait_group 0;" ::: "memory")

// ---------------- prep kernels (split into bf16 planes) ----------------------
__global__ void prep_w(const float* pW1, const float* pW2, const float* dW1,
                       const float* aW, const float* cW1, const float* cW2)
{
    int id = blockIdx.x;
    const float* W;
    if      (id < 6)   W = pW1 + id * 16384;
    else if (id < 12)  W = pW2 + (id - 6) * 16384;
    else if (id == 12) W = dW1;
    else if (id == 13) W = aW;
    else if (id == 14) W = aW + 16384;
    else if (id == 15) W = cW1;
    else               W = cW2;
    __nv_bfloat16* hi = WSP + id * 32768;
    __nv_bfloat16* lo = hi + 16384;
    for (int idx = threadIdx.x; idx < 16384; idx += blockDim.x) {
        int n = idx >> 7, k = idx & 127;
        float x = W[k * 128 + n];
        __nv_bfloat16 h = __float2bfloat16(x);
        float r = x - __uint_as_float(((u32)__bfloat16_as_ushort(h)) << 16);
        hi[idx] = h;
        lo[idx] = __float2bfloat16(r);
    }
}
__global__ void prep_wo(const float* pWo) {
    int y = blockIdx.x;
    __nv_bfloat16* hi = WOSP + y * 32768;
    __nv_bfloat16* lo = hi + 16384;
    for (int idx = threadIdx.x; idx < 16384; idx += blockDim.x) {
        int o = idx >> 7, k = idx & 127;
        float x = (o < 60) ? pWo[y * 7680 + k * 60 + o] : 0.f;
        __nv_bfloat16 h = __float2bfloat16(x);
        float r = x - __uint_as_float(((u32)__bfloat16_as_ushort(h)) << 16);
        hi[idx] = h;
        lo[idx] = __float2bfloat16(r);
    }
}
__global__ void prep_x(const float* a, int n) {
    int i = blockIdx.x * blockDim.x + threadIdx.x;
    if (i < n) {
        float x = a[i];
        __nv_bfloat16 h = __float2bfloat16(x);
        float r = x - __uint_as_float(((u32)__bfloat16_as_ushort(h)) << 16);
        XPH[i] = h;
        XPL[i] = __float2bfloat16(r);
    }
}

// ---------------- staging (pure cp.async) ------------------------------------
__device__ __forceinline__ void stageA_cpa(u32 sb, int tid, int row0, int M) {
    #pragma unroll
    for (int i = 0; i < 8; i++) {
        int idx = tid + 256 * i;               // 2048 chunks per plane
        int r = idx >> 4, c = (idx & 15) * 16;
        int gr = row0 + r;
        int sz = gr < M ? 16 : 0;
        int grc = gr < M ? gr : 0;
        cpa16(sb + OF_AH + r * RS + c, (const char*)(XPH + (size_t)grc * 128) + c, sz);
        cpa16(sb + OF_AL + r * RS + c, (const char*)(XPL + (size_t)grc * 128) + c, sz);
    }
}
// stage one k-half (k0 in {0,64} bf16 elems) of a 2-plane W image
__device__ __forceinline__ void stageW_cpa(const __nv_bfloat16* Wp, int k0, u32 sb, int tid) {
    #pragma unroll
    for (int i = 0; i < 8; i++) {
        int idx = tid + 256 * i;               // 2048 = 2 planes x 1024
        int plane = idx >> 10, rem = idx & 1023;
        int r = rem >> 3, c = (rem & 7) * 16;
        const char* src = (const char*)(Wp + plane * 16384 + r * 128 + k0) + c;
        cpa16(sb + (plane ? OF_WL : OF_WH) + r * WRS + c, src, 16);
    }
}

// ---------------- MMA over one W k-half --------------------------------------
template <int MT>
__device__ __forceinline__ void mma_half(const char* smc, int rbase, int nbase,
                                         int g, int tg, int ks0, float (&acc)[MT][4][4])
{
    const char* Ahi = smc + OF_AH; const char* Alo = smc + OF_AL;
    const char* Wh  = smc + OF_WH; const char* Wl  = smc + OF_WL;
    #pragma unroll
    for (int kh = 0; kh < 4; kh++) {
        const int cA = ((ks0 + kh) * 16 + tg * 2) * 2;
        const int cW = (kh * 16 + tg * 2) * 2;
        u32 bh[4][2], bl[4][2];
        #pragma unroll
        for (int nt = 0; nt < 4; nt++) {
            int nb = (nbase + nt * 8 + g) * WRS;
            bh[nt][0] = *(const u32*)(Wh + nb + cW);
            bh[nt][1] = *(const u32*)(Wh + nb + cW + 16);
            bl[nt][0] = *(const u32*)(Wl + nb + cW);
            bl[nt][1] = *(const u32*)(Wl + nb + cW + 16);
        }
        #pragma unroll
        for (int mt = 0; mt < MT; mt++) {
            int rb = (rbase + mt * 16 + g) * RS;
            u32 ah[4] = { *(const u32*)(Ahi + rb + cA), *(const u32*)(Ahi + rb + 8 * RS + cA),
                          *(const u32*)(Ahi + rb + cA + 16), *(const u32*)(Ahi + rb + 8 * RS + cA + 16) };
            u32 al[4] = { *(const u32*)(Alo + rb + cA), *(const u32*)(Alo + rb + 8 * RS + cA),
                          *(const u32*)(Alo + rb + cA + 16), *(const u32*)(Alo + rb + 8 * RS + cA + 16) };
            #pragma unroll
            for (int nt = 0; nt < 4; nt++) {
                mma16816(acc[mt][nt], ah, bh[nt]);
                mma16816(acc[mt][nt], al, bh[nt]);
                mma16816(acc[mt][nt], ah, bl[nt]);
            }
        }
    }
}

// ---------------- accumulator epilogue (GN/res/relu/dot/writes) --------------
// Prefetches nextW half-1 under the epilogue (only legal when gb4 != null,
// since the GN __syncthreads proves all W-buffer reads are done).
__device__ __forceinline__ void epi_main(
    char* smc, u32 sb, float (&acc)[4][4][4],
    int tid, int wm, int wn, int g, int tg, int row0, int M,
    const float4* gb4, const float* pre, const float* post, int relu,
    const float2* wv2, const float* wob, float* dot,
    float* outF, int writeA, const __nv_bfloat16* nextW)
{
    float2* sred = (float2*)(smc + 4608);
    const int cbase = wn * 32 + tg * 2;
    const int rloc0 = wm * 64 + g;

    if (pre) {
        #pragma unroll
        for (int mt = 0; mt < 4; mt++)
        #pragma unroll
        for (int h = 0; h < 2; h++) {
            int R = row0 + rloc0 + mt * 16 + 8 * h;
            if (R < M) {
                const float* pr = pre + (size_t)(R / 6) * 128;
                #pragma unroll
                for (int nt = 0; nt < 4; nt++) {
                    float2 a = *(const float2*)(pr + cbase + nt * 8);
                    acc[mt][nt][2*h] += a.x; acc[mt][nt][2*h+1] += a.y;
                }
            }
        }
    }
    if (gb4) {
        #pragma unroll
        for (int mt = 0; mt < 4; mt++)
        #pragma unroll
        for (int h = 0; h < 2; h++) {
            float s = 0.f, ss = 0.f;
            #pragma unroll
            for (int nt = 0; nt < 4; nt++) {
                float x = acc[mt][nt][2*h], yv = acc[mt][nt][2*h+1];
                s += x + yv; ss += x * x + yv * yv;
            }
            s += __shfl_xor_sync(~0u, s, 1); ss += __shfl_xor_sync(~0u, ss, 1);
            s += __shfl_xor_sync(~0u, s, 2); ss += __shfl_xor_sync(~0u, ss, 2);
            if (tg == 0) sred[(rloc0 + mt * 16 + 8 * h) * 4 + wn] = make_float2(s, ss);
        }
        __syncthreads();
        if (nextW) { stageW_cpa(nextW, 0, sb, tid); CPA_COMMIT(); }
        float mv[4][2], iv[4][2];
        #pragma unroll
        for (int mt = 0; mt < 4; mt++)
        #pragma unroll
        for (int h = 0; h < 2; h++) {
            int rl = (rloc0 + mt * 16 + 8 * h) * 4;
            float2 t0 = sred[rl], t1 = sred[rl+1], t2 = sred[rl+2], t3 = sred[rl+3];
            float s = t0.x + t1.x + t2.x + t3.x, ss = t0.y + t1.y + t2.y + t3.y;
            float m = s * (1.f / 128.f);
            mv[mt][h] = m;
            iv[mt][h] = rsqrtf(ss * (1.f / 128.f) - m * m + EPS);
        }
        #pragma unroll
        for (int nt = 0; nt < 4; nt++) {
            float4 q = gb4[(cbase + nt * 8) >> 1];
            #pragma unroll
            for (int mt = 0; mt < 4; mt++)
            #pragma unroll
            for (int h = 0; h < 2; h++) {
                acc[mt][nt][2*h]   = (acc[mt][nt][2*h]   - mv[mt][h]) * iv[mt][h] * q.x + q.y;
                acc[mt][nt][2*h+1] = (acc[mt][nt][2*h+1] - mv[mt][h]) * iv[mt][h] * q.z + q.w;
            }
        }
    }
    if (post) {
        #pragma unroll
        for (int mt = 0; mt < 4; mt++)
        #pragma unroll
        for (int h = 0; h < 2; h++) {
            int R = row0 + rloc0 + mt * 16 + 8 * h;
            if (R < M) {
                const float* pr = post + (size_t)R * 128;
                #pragma unroll
                for (int nt = 0; nt < 4; nt++) {
                    float2 a = *(const float2*)(pr + cbase + nt * 8);
                    acc[mt][nt][2*h] += a.x; acc[mt][nt][2*h+1] += a.y;
                }
            }
        }
    }
    if (relu) {
        #pragma unroll
        for (int mt = 0; mt < 4; mt++)
        #pragma unroll
        for (int nt = 0; nt < 4; nt++)
        #pragma unroll
        for (int q = 0; q < 4; q++) acc[mt][nt][q] = fmaxf(acc[mt][nt][q], 0.f);
    }
    if (wv2) {
        __syncthreads();             // GN sred reads done before reuse
        #pragma unroll
        for (int mt = 0; mt < 4; mt++)
        #pragma unroll
        for (int h = 0; h < 2; h++) {
            float d = 0.f;
            #pragma unroll
            for (int nt = 0; nt < 4; nt++) {
                float2 w = wv2[(cbase + nt * 8) >> 1];
                d += acc[mt][nt][2*h] * w.x + acc[mt][nt][2*h+1] * w.y;
            }
            d += __shfl_xor_sync(~0u, d, 1);
            d += __shfl_xor_sync(~0u, d, 2);
            if (tg == 0) sred[(rloc0 + mt * 16 + 8 * h) * 4 + wn].x = d;
        }
        __syncthreads();
        if (wn == 0 && tg == 0) {
            #pragma unroll
            for (int mt = 0; mt < 4; mt++)
            #pragma unroll
            for (int h = 0; h < 2; h++) {
                int rl = (rloc0 + mt * 16 + 8 * h) * 4;
                float t = sred[rl].x + sred[rl+1].x + sred[rl+2].x + sred[rl+3].x;
                int R = row0 + rloc0 + mt * 16 + 8 * h;
                if (R < M) dot[R] = t + wob[0];
            }
        }
    }
    if (outF) {
        #pragma unroll
        for (int mt = 0; mt < 4; mt++)
        #pragma unroll
        for (int h = 0; h < 2; h++) {
            int R = row0 + rloc0 + mt * 16 + 8 * h;
            if (R < M) {
                float* o = outF + (size_t)R * 128;
                #pragma unroll
                for (int nt = 0; nt < 4; nt++)
                    *(float2*)(o + cbase + nt * 8) = make_float2(acc[mt][nt][2*h], acc[mt][nt][2*h+1]);
            }
        }
    }
    if (writeA) {
        char* Ahi = smc + OF_AH; char* Alo = smc + OF_AL;
        #pragma unroll
        for (int mt = 0; mt < 4; mt++)
        #pragma unroll
        for (int h = 0; h < 2; h++) {
            int rl = rloc0 + mt * 16 + 8 * h;
            char* hp = Ahi + rl * RS;
            char* lp = Alo + rl * RS;
            #pragma unroll
            for (int nt = 0; nt < 4; nt++) {
                int c = cbase + nt * 8;
                u32 p0 = packbf(acc[mt][nt][2*h]), p1 = packbf(acc[mt][nt][2*h+1]);
                *(u32*)(hp + c * 2) = (p0 >> 16) | (p1 & 0xffff0000u);
                *(u32*)(lp + c * 2) = (p0 & 0xffffu) | (p1 << 16);
            }
        }
    }
}

// ---------------- one fused 128x128 stage ------------------------------------
// Entry contract: this stage's W half-1 cp.async is in flight (committed).
__device__ __forceinline__ void stage128(
    char* smc, u32 sb, const __nv_bfloat16* Wsrc, const __nv_bfloat16* nextW,
    int tid, int row0, int M,
    const float4* gb4, const float* pre, const float* post, int relu,
    const float2* wv2, const float* wob, float* dot, float* outF, int writeA)
{
    const int wid = tid >> 5, lane = tid & 31;
    const int wm = wid >> 2, wn = wid & 3, g = lane >> 2, tg = lane & 3;
    float acc[4][4][4];
    #pragma unroll
    for (int i = 0; i < 4; i++)
        #pragma unroll
        for (int j = 0; j < 4; j++)
            #pragma unroll
            for (int q = 0; q < 4; q++) acc[i][j][q] = 0.f;

    CPA_WAIT0();
    __syncthreads();                               // W half-1 (and A) visible
    mma_half<4>(smc, wm * 64, wn * 32, g, tg, 0, acc);
    __syncthreads();                               // all reads of half-1 done
    stageW_cpa(Wsrc, 64, sb, tid); CPA_COMMIT(); CPA_WAIT0();
    __syncthreads();
    mma_half<4>(smc, wm * 64, wn * 32, g, tg, 4, acc);
    epi_main(smc, sb, acc, tid, wm, wn, g, tg, row0, M, gb4, pre, post, relu,
             wv2, wob, dot, outF, writeA, nextW);
    __syncthreads();
}

// ---------------- K1: fused pred head ----------------------------------------
__global__ void __launch_bounds__(256, 2) k_pred(
    const float* actors, const float* pg1, const float* pb1,
    const float* pg2, const float* pb2, const float* pbo, int N)
{
    extern __shared__ char smc[];
    float4* gb0 = (float4*)smc;
    float4* gb1 = (float4*)(smc + 1024);
    float2* bias2 = (float2*)(smc + 4096);
    const u32 sb = smem_u32p(smc);
    const int tid = threadIdx.x;
    const int y = blockIdx.y, row0 = blockIdx.x * 128;

    stageA_cpa(sb, tid, row0, N);
    stageW_cpa(WSP + y * 32768, 0, sb, tid);
    CPA_COMMIT();

    if (tid < 64) {
        int c = 2 * tid;
        gb0[tid] = make_float4(pg1[y*128+c], pb1[y*128+c], pg1[y*128+c+1], pb1[y*128+c+1]);
        gb1[tid] = make_float4(pg2[y*128+c], pb2[y*128+c], pg2[y*128+c+1], pb2[y*128+c+1]);
    }
    if (tid < 32) {
        int c = 2 * tid;
        bias2[tid] = make_float2(c < 60 ? pbo[y*60+c] : 0.f, c+1 < 60 ? pbo[y*60+c+1] : 0.f);
    }

    stage128(smc, sb, WSP + y * 32768, WSP + (6 + y) * 32768, tid, row0, N,
             gb0, nullptr, nullptr, 1, nullptr, nullptr, nullptr, nullptr, 1);
    stage128(smc, sb, WSP + (6 + y) * 32768, WOSP + y * 32768, tid, row0, N,
             gb1, nullptr, actors, 1, nullptr, nullptr, nullptr, nullptr, 1);

    // stage 2: preds = h @ Wo + bias (n=64 staged rows, cols 0..59 valid)
    {
        const int wid = tid >> 5, lane = tid & 31;
        const int g = lane >> 2, tg = lane & 3;
        const int rbase = (wid >> 1) * 32, nbase = (wid & 1) * 32;
        float acc[2][4][4];
        #pragma unroll
        for (int i = 0; i < 2; i++)
            #pragma unroll
            for (int j = 0; j < 4; j++)
                #pragma unroll
                for (int q = 0; q < 4; q++) acc[i][j][q] = 0.f;
        CPA_WAIT0();
        __syncthreads();                           // Wo half-1 visible (prefetched)
        mma_half<2>(smc, rbase, nbase, g, tg, 0, acc);
        __syncthreads();
        stageW_cpa(WOSP + y * 32768, 64, sb, tid); CPA_COMMIT(); CPA_WAIT0();
        __syncthreads();
        mma_half<2>(smc, rbase, nbase, g, tg, 4, acc);
        #pragma unroll
        for (int mt = 0; mt < 2; mt++)
        #pragma unroll
        for (int h = 0; h < 2; h++) {
            int R = row0 + rbase + mt * 16 + g + 8 * h;
            if (R < N) {
                float* o = S3 + (size_t)R * 360 + y * 60;
                #pragma unroll
                for (int nt = 0; nt < 4; nt++) {
                    int c = nbase + nt * 8 + tg * 2;
                    if (c < 60) {
                        float2 bb = bias2[c >> 1];
                        o[c]     = acc[mt][nt][2*h]   + bb.x;
                        o[c + 1] = acc[mt][nt][2*h+1] + bb.y;
                    }
                }
            }
        }
    }
}

// ---------------- K2: actB = actors @ agt_W[128:256] -------------------------
__global__ void __launch_bounds__(256, 2) k_actB(int N)
{
    extern __shared__ char smc[];
    const u32 sb = smem_u32p(smc);
    const int tid = threadIdx.x;
    const int row0 = blockIdx.x * 128;

    stageA_cpa(sb, tid, row0, N);
    stageW_cpa(WSP + 14 * 32768, 0, sb, tid);
    CPA_COMMIT();

    stage128(smc, sb, WSP + 14 * 32768, nullptr, tid, row0, N,
             nullptr, nullptr, nullptr, 0, nullptr, nullptr, nullptr, S5, 0);
}

// ---------------- K3: fused chain (dist -> agt -> cls1 -> cls2) --------------
__global__ void __launch_bounds__(256, 2) k_chain(
    const float* dW0, const float* db0, const float* dg1, const float* db1v,
    const float* ag, const float* ab, const float* cg1, const float* cb1,
    const float* cg2, const float* cb2, const float* cWo, const float* cbo,
    float* feats, int M)
{
    extern __shared__ char smc[];
    float4* gbA = (float4*)smc;
    float4* gbB = (float4*)(smc + 1024);
    float4* gbC = (float4*)(smc + 2048);
    float4* gbD = (float4*)(smc + 3072);
    float2* wv2 = (float2*)(smc + 4096);
    float* w0a = (float*)(smc + 4608);
    float* w0b = (float*)(smc + 5120);
    float* b0v = (float*)(smc + 5632);
    float* pav = (float*)(smc + 6144);
    float* pbv = (float*)(smc + 6656);
    char* Ahi = smc + OF_AH; char* Alo = smc + OF_AL;
    const u32 sb = smem_u32p(smc);

    const int tid = threadIdx.x;
    const int row0 = blockIdx.x * 128;

    stageW_cpa(WSP + 12 * 32768, 0, sb, tid);
    CPA_COMMIT();

    if (tid < 64) {
        int c = 2 * tid;
        gbA[tid] = make_float4(dg1[c], db1v[c], dg1[c+1], db1v[c+1]);
        gbB[tid] = make_float4(ag[c],  ab[c],   ag[c+1],  ab[c+1]);
        gbC[tid] = make_float4(cg1[c], cb1[c],  cg1[c+1], cb1[c+1]);
        gbD[tid] = make_float4(cg2[c], cb2[c],  cg2[c+1], cb2[c+1]);
        wv2[tid] = make_float2(cWo[c], cWo[c+1]);
    }
    if (tid < 128) {
        w0a[tid] = dW0[tid]; w0b[tid] = dW0[128 + tid]; b0v[tid] = db0[tid];
        int R = row0 + tid; float a = 0.f, bq = 0.f;
        if (R < M) { a = S3[(size_t)R * 60 + 58]; bq = S3[(size_t)R * 60 + 59]; }
        pav[tid] = a; pbv[tid] = bq;
    }
    __syncthreads();

    // generate dist A: relu(b0 - p58*W0[0] - p59*W0[1])
    #pragma unroll
    for (int it = 0; it < 32; it++) {
        int idx = tid + it * 256;
        int r = idx >> 6, k2 = (idx & 63) * 2;
        float x0 = fmaxf(b0v[k2]     - pav[r] * w0a[k2]     - pbv[r] * w0b[k2],     0.f);
        float x1 = fmaxf(b0v[k2 + 1] - pav[r] * w0a[k2 + 1] - pbv[r] * w0b[k2 + 1], 0.f);
        u32 p0 = packbf(x0), p1 = packbf(x1);
        int off = r * RS + k2 * 2;
        *(u32*)(Ahi + off) = (p0 >> 16) | (p1 & 0xffff0000u);
        *(u32*)(Alo + off) = (p0 & 0xffffu) | (p1 << 16);
    }

    stage128(smc, sb, WSP + 12 * 32768, WSP + 13 * 32768, tid, row0, M,
             gbA, nullptr, nullptr, 1, nullptr, nullptr, nullptr, nullptr, 1);
    stage128(smc, sb, WSP + 13 * 32768, WSP + 15 * 32768, tid, row0, M,
             gbB, S5, nullptr, 1, nullptr, nullptr, nullptr, feats, 1);
    stage128(smc, sb, WSP + 15 * 32768, WSP + 16 * 32768, tid, row0, M,
             gbC, nullptr, nullptr, 1, nullptr, nullptr, nullptr, nullptr, 1);
    stage128(smc, sb, WSP + 16 * 32768, nullptr, tid, row0, M,
             gbD, nullptr, feats, 1, wv2, cbo, S4, nullptr, 0);
}

// ---------------- softmax + rank-sort + reg gather ---------------------------
__global__ void finalize(const float* ctr, float* clsO, float* regO, int N)
{
    int w = (blockIdx.x * blockDim.x + threadIdx.x) >> 5;
    int lane = threadIdx.x & 31;
    if (w >= N) return;
    float v = (lane < 6) ? S4[(size_t)w * 6 + lane] : -3.4e38f;
    float m = v;
    #pragma unroll
    for (int s = 4; s >= 1; s >>= 1) m = fmaxf(m, __shfl_xor_sync(~0u, m, s));
    float e = (lane < 6) ? expf(v - m) : 0.f;
    float s = e;
    #pragma unroll
    for (int t = 4; t >= 1; t >>= 1) s += __shfl_xor_sync(~0u, s, t);
    float pr = e / s;
    int rk = 0;
    #pragma unroll
    for (int j = 0; j < 6; j++) {
        float pj = __shfl_sync(~0u, pr, j);
        rk += (pj > pr) || (pj == pr && j < lane);
    }
    if (lane < 6) clsO[(size_t)w * 6 + rk] = pr;
    float cx = ctr[(size_t)w * 2], cy = ctr[(size_t)w * 2 + 1];
    for (int k = 0; k < 6; k++) {
        int r = __shfl_sync(~0u, rk, k);
        const float* sp = S3 + (size_t)w * 360 + k * 60;
        float* dp = regO + ((size_t)w * 6 + r) * 60;
        for (int j = lane; j < 60; j += 32) dp[j] = sp[j] + ((j & 1) ? cy : cx);
    }
}

// ---------------- host orchestration ----------------------------------------
extern "C" void kernel_launch(void* const* d_in, const int* in_sizes, int n_in,
                              void* d_out, int out_size)
{
    const float* actors = (const float*)d_in[0];
    const float* ctrs   = (const float*)d_in[1];
    const float* pW1 = (const float*)d_in[2];
    const float* pg1 = (const float*)d_in[3];
    const float* pb1 = (const float*)d_in[4];
    const float* pW2 = (const float*)d_in[5];
    const float* pg2 = (const float*)d_in[6];
    const float* pb2 = (const float*)d_in[7];
    const float* pWo = (const float*)d_in[8];
    const float* pbo = (const float*)d_in[9];
    const float* dW0 = (const float*)d_in[10];
    const float* db0 = (const float*)d_in[11];
    const float* dW1 = (const float*)d_in[12];
    const float* dg1 = (const float*)d_in[13];
    const float* db1 = (const float*)d_in[14];
    const float* aW  = (const float*)d_in[15];
    const float* ag  = (const float*)d_in[16];
    const float* ab  = (const float*)d_in[17];
    const float* cW1 = (const float*)d_in[18];
    const float* cg1 = (const float*)d_in[19];
    const float* cb1 = (const float*)d_in[20];
    const float* cW2 = (const float*)d_in[21];
    const float* cg2 = (const float*)d_in[22];
    const float* cb2 = (const float*)d_in[23];
    const float* cWo = (const float*)d_in[24];
    const float* cbo = (const float*)d_in[25];

    const int N = in_sizes[0] / 128;       // 100000
    const int M = N * 6;
    const int gN = (N + 127) / 128, gM = (M + 127) / 128;
    float* out   = (float*)d_out;
    float* regO  = out + (size_t)N * 6;
    float* feats = regO + (size_t)N * 360;

    float *s3, *s4, *s5;
    cudaGetSymbolAddress((void**)&s3, S3);
    cudaGetSymbolAddress((void**)&s4, S4);
    cudaGetSymbolAddress((void**)&s5, S5);
    (void)s3; (void)s4; (void)s5;

    cudaFuncSetAttribute(k_pred,  cudaFuncAttributeMaxDynamicSharedMemorySize, SMEMB);
    cudaFuncSetAttribute(k_actB,  cudaFuncAttributeMaxDynamicSharedMemorySize, SMEMB);
    cudaFuncSetAttribute(k_chain, cudaFuncAttributeMaxDynamicSharedMemorySize, SMEMB);

    prep_w<<<17, 128>>>(pW1, pW2, dW1, aW, cW1, cW2);
    prep_wo<<<6, 128>>>(pWo);
    prep_x<<<(N * 128 + 255) / 256, 256>>>(actors, N * 128);

    k_pred<<<dim3(gN, 6), 256, SMEMB>>>(actors, pg1, pb1, pg2, pb2, pbo, N);
    k_actB<<<gN, 256, SMEMB>>>(N);
    k_chain<<<gM, 256, SMEMB>>>(dW0, db0, dg1, db1, ag, ab, cg1, cb1,
                                cg2, cb2, cWo, cbo, feats, M);
    finalize<<<(N + 7) / 8, 256>>>(ctrs, out, regO, N);
}

// round 16
// speedup vs baseline: 2.6060x; 1.0680x over previous
#include <cuda_runtime.h>
#include <cuda_bf16.h>
#include <cstdint>

typedef unsigned long long u64;
typedef long long i64;
typedef uint32_t u32;

#define EPS 1e-5f
#define VEC 8704
#define OF_AH VEC                    // A hi plane: 64 tiles x 512B = 32768
#define OF_AL (OF_AH + 32768)
#define OF_WH (OF_AL + 32768)        // W hi half:  64 tiles x 256B = 16384
#define OF_WL (OF_WH + 16384)
#define SMEMB (OF_WL + 16384)        // 107008 -> 2 CTAs/SM

#define NBMAX 800

// ---------------- scratch (device globals; no runtime alloc) ----------------
__device__ __align__(16) u32 XPHU[NBMAX * 8192];    // actors hi plane, fragment-major
__device__ __align__(16) u32 XPLU[NBMAX * 8192];    // actors lo plane
__device__ __align__(16) u32 WSPU[17 * 16384];      // W: [id][plane][half][n8][ksh][lane][j]
__device__ __align__(16) u32 WOSPU[6 * 16384];      // Wo images, same layout
__device__ __align__(16) float S3[600000u * 60];    // preds
__device__ __align__(16) float S4[600000];          // cls logits
__device__ __align__(16) float S5[100000u * 128];   // actB fp32

// ---------------- helpers ----------------------------------------------------
__device__ __forceinline__ u32 packbf(float x) {
    u32 hb = (u32)__bfloat16_as_ushort(__float2bfloat16(x));
    float r = x - __uint_as_float(hb << 16);
    return (hb << 16) | (u32)__bfloat16_as_ushort(__float2bfloat16(r));
}
__device__ __forceinline__ void mma16816(float* c, const u32* a, const u32* b) {
    asm volatile(
        "mma.sync.aligned.m16n8k16.row.col.f32.bf16.bf16.f32 "
        "{%0,%1,%2,%3}, {%4,%5,%6,%7}, {%8,%9}, {%0,%1,%2,%3};"
        : "+f"(c[0]), "+f"(c[1]), "+f"(c[2]), "+f"(c[3])
        : "r"(a[0]), "r"(a[1]), "r"(a[2]), "r"(a[3]), "r"(b[0]), "r"(b[1]));
}
__device__ __forceinline__ u32 smem_u32p(const void* p) {
    u32 a;
    asm("{ .reg .u64 t; cvta.to.shared.u64 t, %1; cvt.u32.u64 %0, t; }" : "=r"(a) : "l"(p));
    return a;
}
__device__ __forceinline__ void cpa16(u32 dst, const void* src, int sz) {
    asm volatile("cp.async.ca.shared.global [%0], [%1], 16, %2;"
                 :: "r"(dst), "l"(src), "r"(sz) : "memory");
}
#define CPA_COMMIT() asm volatile("cp.async.commit_group;" ::: "memory")
#define CPA_WAIT0()  asm volatile("cp.async.wait_group 0;" ::: "memory")

// ---------------- prep kernels (fragment-major global images) ----------------
// W image per plane (8192 u32): off = half*4096 + (n8*4+ksh)*64 + lane*2 + j
__global__ void prep_w(const float* pW1, const float* pW2, const float* dW1,
                       const float* aW, const float* cW1, const float* cW2)
{
    int id = blockIdx.x;
    const float* W;
    if      (id < 6)   W = pW1 + id * 16384;
    else if (id < 12)  W = pW2 + (id - 6) * 16384;
    else if (id == 12) W = dW1;
    else if (id == 13) W = aW;
    else if (id == 14) W = aW + 16384;
    else if (id == 15) W = cW1;
    else               W = cW2;
    for (int idx = threadIdx.x; idx < 8192; idx += blockDim.x) {
        int n = idx >> 6, p = idx & 63;                  // B row n, k-pair p
        float x0 = W[(2 * p) * 128 + n];                 // B[n][k] = W[k][n]
        float x1 = W[(2 * p + 1) * 128 + n];
        u32 p0 = packbf(x0), p1 = packbf(x1);
        int n8 = n >> 3, gg = n & 7;
        int ks = p >> 3, pin = p & 7, j = pin >> 2, tg = pin & 3;
        u32 off = (u32)(ks >> 2) * 4096 + ((n8 * 4 + (ks & 3)) * 64) + (gg * 4 + tg) * 2 + j;
        WSPU[id * 16384u + off]        = (p0 >> 16) | (p1 & 0xffff0000u);
        WSPU[id * 16384u + 8192 + off] = (p0 & 0xffffu) | (p1 << 16);
    }
}
__global__ void prep_wo(const float* pWo) {
    int y = blockIdx.x;
    for (int idx = threadIdx.x; idx < 8192; idx += blockDim.x) {
        int o = idx >> 6, p = idx & 63;
        float x0 = (o < 60) ? pWo[y * 7680 + (2 * p) * 60 + o] : 0.f;
        float x1 = (o < 60) ? pWo[y * 7680 + (2 * p + 1) * 60 + o] : 0.f;
        u32 p0 = packbf(x0), p1 = packbf(x1);
        int n8 = o >> 3, gg = o & 7;
        int ks = p >> 3, pin = p & 7, j = pin >> 2, tg = pin & 3;
        u32 off = (u32)(ks >> 2) * 4096 + ((n8 * 4 + (ks & 3)) * 64) + (gg * 4 + tg) * 2 + j;
        WOSPU[y * 16384u + off]        = (p0 >> 16) | (p1 & 0xffff0000u);
        WOSPU[y * 16384u + 8192 + off] = (p0 & 0xffffu) | (p1 << 16);
    }
}
// A image per 128-row block (8192 u32/plane): tile(r16,ks)*128 + slot(lane)*4 + h + 2*kj
__global__ void prep_x(const float* a, int N, int NB) {
    int idx = blockIdx.x * blockDim.x + threadIdx.x;
    if (idx >= NB * 8192) return;
    int r = idx >> 6, p = idx & 63;
    float x0 = 0.f, x1 = 0.f;
    if (r < N) { x0 = a[(size_t)r * 128 + 2 * p]; x1 = a[(size_t)r * 128 + 2 * p + 1]; }
    u32 p0 = packbf(x0), p1 = packbf(x1);
    int blk = r >> 7, ri = r & 127;
    int r16 = ri >> 4, rq = ri & 15, h = rq >> 3, gg = rq & 7;
    int ks = p >> 3, pin = p & 7, kj = pin >> 2, tg = pin & 3;
    int lane = gg * 4 + tg; lane ^= (lane >> 3);
    u32 off = (u32)blk * 8192 + (r16 * 8 + ks) * 128 + lane * 4 + h + 2 * kj;
    XPHU[off] = (p0 >> 16) | (p1 & 0xffff0000u);
    XPLU[off] = (p0 & 0xffffu) | (p1 << 16);
}

// ---------------- staging (verbatim cp.async copies) --------------------------
__device__ __forceinline__ void stageA_cpa(u32 sb, int tid, int blk) {
    const u32* sH = XPHU + (size_t)blk * 8192;
    const u32* sL = XPLU + (size_t)blk * 8192;
    #pragma unroll
    for (int i = 0; i < 8; i++) {
        int idx = tid + 256 * i;                       // 2048 chunks / plane
        cpa16(sb + OF_AH + idx * 16, sH + idx * 4, 16);
        cpa16(sb + OF_AL + idx * 16, sL + idx * 4, 16);
    }
}
__device__ __forceinline__ void stageW_cpa(const u32* Wp, int half, u32 sb, int tid) {
    const u32* h0 = Wp + half * 4096;
    #pragma unroll
    for (int i = 0; i < 4; i++) {
        int idx = tid + 256 * i;                       // 1024 chunks / plane
        cpa16(sb + OF_WH + idx * 16, h0 + idx * 4, 16);
        cpa16(sb + OF_WL + idx * 16, h0 + 8192 + idx * 4, 16);
    }
}

// ---------------- MMA over one W k-half (fragment-major loads) ---------------
template <int MT>
__device__ __forceinline__ void mma_half(const char* smc, int rbase, int nbase,
                                         int lane, int ks0, float (&acc)[MT][4][4])
{
    const char* Ahi = smc + OF_AH; const char* Alo = smc + OF_AL;
    const char* Wh  = smc + OF_WH; const char* Wl  = smc + OF_WL;
    const int sl = (lane ^ (lane >> 3)) * 16;
    const int wl = lane * 8;
    #pragma unroll
    for (int kh = 0; kh < 4; kh++) {
        u32 bh[4][2], bl[4][2];
        #pragma unroll
        for (int nt = 0; nt < 4; nt++) {
            int off = (((nbase >> 3) + nt) * 4 + kh) * 256 + wl;
            uint2 t = *(const uint2*)(Wh + off); bh[nt][0] = t.x; bh[nt][1] = t.y;
            uint2 u = *(const uint2*)(Wl + off); bl[nt][0] = u.x; bl[nt][1] = u.y;
        }
        #pragma unroll
        for (int mt = 0; mt < MT; mt++) {
            int aoff = ((((rbase >> 4) + mt) * 8) + ks0 + kh) * 512 + sl;
            uint4 qh = *(const uint4*)(Ahi + aoff);
            uint4 ql = *(const uint4*)(Alo + aoff);
            u32 ah[4] = {qh.x, qh.y, qh.z, qh.w};
            u32 al[4] = {ql.x, ql.y, ql.z, ql.w};
            #pragma unroll
            for (int nt = 0; nt < 4; nt++) {
                mma16816(acc[mt][nt], ah, bh[nt]);
                mma16816(acc[mt][nt], al, bh[nt]);
                mma16816(acc[mt][nt], ah, bl[nt]);
            }
        }
    }
}

// ---------------- accumulator epilogue (GN/res/relu/dot/writes) ---------------
// Prefetches nextW half-0 under the epilogue (legal only when gb4 != null).
__device__ __forceinline__ void epi_main(
    char* smc, u32 sb, float (&acc)[4][4][4],
    int tid, int wm, int wn, int g, int tg, int row0, int M,
    const float4* gb4, const float* pre, const float* post, int relu,
    const float2* wv2, const float* wob, float* dot,
    float* outF, int writeA, const u32* nextW)
{
    float2* sred = (float2*)(smc + 4608);
    const int lane = tid & 31;
    const int cbase = wn * 32 + tg * 2;
    const int rloc0 = wm * 64 + g;

    if (pre) {
        #pragma unroll
        for (int mt = 0; mt < 4; mt++)
        #pragma unroll
        for (int h = 0; h < 2; h++) {
            int R = row0 + rloc0 + mt * 16 + 8 * h;
            if (R < M) {
                const float* pr = pre + (size_t)(R / 6) * 128;
                #pragma unroll
                for (int nt = 0; nt < 4; nt++) {
                    float2 a = *(const float2*)(pr + cbase + nt * 8);
                    acc[mt][nt][2*h] += a.x; acc[mt][nt][2*h+1] += a.y;
                }
            }
        }
    }
    if (gb4) {
        #pragma unroll
        for (int mt = 0; mt < 4; mt++)
        #pragma unroll
        for (int h = 0; h < 2; h++) {
            float s = 0.f, ss = 0.f;
            #pragma unroll
            for (int nt = 0; nt < 4; nt++) {
                float x = acc[mt][nt][2*h], yv = acc[mt][nt][2*h+1];
                s += x + yv; ss += x * x + yv * yv;
            }
            s += __shfl_xor_sync(~0u, s, 1); ss += __shfl_xor_sync(~0u, ss, 1);
            s += __shfl_xor_sync(~0u, s, 2); ss += __shfl_xor_sync(~0u, ss, 2);
            if (tg == 0) sred[(rloc0 + mt * 16 + 8 * h) * 4 + wn] = make_float2(s, ss);
        }
        __syncthreads();
        if (nextW) { stageW_cpa(nextW, 0, sb, tid); CPA_COMMIT(); }
        float mv[4][2], iv[4][2];
        #pragma unroll
        for (int mt = 0; mt < 4; mt++)
        #pragma unroll
        for (int h = 0; h < 2; h++) {
            int rl = (rloc0 + mt * 16 + 8 * h) * 4;
            float2 t0 = sred[rl], t1 = sred[rl+1], t2 = sred[rl+2], t3 = sred[rl+3];
            float s = t0.x + t1.x + t2.x + t3.x, ss = t0.y + t1.y + t2.y + t3.y;
            float m = s * (1.f / 128.f);
            mv[mt][h] = m;
            iv[mt][h] = rsqrtf(ss * (1.f / 128.f) - m * m + EPS);
        }
        #pragma unroll
        for (int nt = 0; nt < 4; nt++) {
            float4 q = gb4[(cbase + nt * 8) >> 1];
            #pragma unroll
            for (int mt = 0; mt < 4; mt++)
            #pragma unroll
            for (int h = 0; h < 2; h++) {
                acc[mt][nt][2*h]   = (acc[mt][nt][2*h]   - mv[mt][h]) * iv[mt][h] * q.x + q.y;
                acc[mt][nt][2*h+1] = (acc[mt][nt][2*h+1] - mv[mt][h]) * iv[mt][h] * q.z + q.w;
            }
        }
    }
    if (post) {
        #pragma unroll
        for (int mt = 0; mt < 4; mt++)
        #pragma unroll
        for (int h = 0; h < 2; h++) {
            int R = row0 + rloc0 + mt * 16 + 8 * h;
            if (R < M) {
                const float* pr = post + (size_t)R * 128;
                #pragma unroll
                for (int nt = 0; nt < 4; nt++) {
                    float2 a = *(const float2*)(pr + cbase + nt * 8);
                    acc[mt][nt][2*h] += a.x; acc[mt][nt][2*h+1] += a.y;
                }
            }
        }
    }
    if (relu) {
        #pragma unroll
        for (int mt = 0; mt < 4; mt++)
        #pragma unroll
        for (int nt = 0; nt < 4; nt++)
        #pragma unroll
        for (int q = 0; q < 4; q++) acc[mt][nt][q] = fmaxf(acc[mt][nt][q], 0.f);
    }
    if (wv2) {
        __syncthreads();
        #pragma unroll
        for (int mt = 0; mt < 4; mt++)
        #pragma unroll
        for (int h = 0; h < 2; h++) {
            float d = 0.f;
            #pragma unroll
            for (int nt = 0; nt < 4; nt++) {
                float2 w = wv2[(cbase + nt * 8) >> 1];
                d += acc[mt][nt][2*h] * w.x + acc[mt][nt][2*h+1] * w.y;
            }
            d += __shfl_xor_sync(~0u, d, 1);
            d += __shfl_xor_sync(~0u, d, 2);
            if (tg == 0) sred[(rloc0 + mt * 16 + 8 * h) * 4 + wn].x = d;
        }
        __syncthreads();
        if (wn == 0 && tg == 0) {
            #pragma unroll
            for (int mt = 0; mt < 4; mt++)
            #pragma unroll
            for (int h = 0; h < 2; h++) {
                int rl = (rloc0 + mt * 16 + 8 * h) * 4;
                float t = sred[rl].x + sred[rl+1].x + sred[rl+2].x + sred[rl+3].x;
                int R = row0 + rloc0 + mt * 16 + 8 * h;
                if (R < M) dot[R] = t + wob[0];
            }
        }
    }
    if (outF) {
        #pragma unroll
        for (int mt = 0; mt < 4; mt++)
        #pragma unroll
        for (int h = 0; h < 2; h++) {
            int R = row0 + rloc0 + mt * 16 + 8 * h;
            if (R < M) {
                float* o = outF + (size_t)R * 128;
                #pragma unroll
                for (int nt = 0; nt < 4; nt++)
                    *(float2*)(o + cbase + nt * 8) = make_float2(acc[mt][nt][2*h], acc[mt][nt][2*h+1]);
            }
        }
    }
    if (writeA) {
        char* Ahi = smc + OF_AH; char* Alo = smc + OF_AL;
        const int sl = (lane ^ (lane >> 3)) * 16;
        #pragma unroll
        for (int mt = 0; mt < 4; mt++)
        #pragma unroll
        for (int nt = 0; nt < 4; nt++) {
            int tile = (wm * 4 + mt) * 8 + wn * 2 + (nt >> 1);
            int off = tile * 512 + sl + (nt & 1) * 8;
            u32 p00 = packbf(acc[mt][nt][0]), p01 = packbf(acc[mt][nt][1]);
            u32 p10 = packbf(acc[mt][nt][2]), p11 = packbf(acc[mt][nt][3]);
            *(uint2*)(Ahi + off) = make_uint2((p00 >> 16) | (p01 & 0xffff0000u),
                                             (p10 >> 16) | (p11 & 0xffff0000u));
            *(uint2*)(Alo + off) = make_uint2((p00 & 0xffffu) | (p01 << 16),
                                             (p10 & 0xffffu) | (p11 << 16));
        }
    }
}

// ---------------- one fused 128x128 stage ------------------------------------
// Entry contract: this stage's W half-0 cp.async is committed.
__device__ __forceinline__ void stage128(
    char* smc, u32 sb, const u32* Wsrc, const u32* nextW,
    int tid, int row0, int M,
    const float4* gb4, const float* pre, const float* post, int relu,
    const float2* wv2, const float* wob, float* dot, float* outF, int writeA)
{
    const int wid = tid >> 5, lane = tid & 31;
    const int wm = wid >> 2, wn = wid & 3, g = lane >> 2, tg = lane & 3;
    float acc[4][4][4];
    #pragma unroll
    for (int i = 0; i < 4; i++)
        #pragma unroll
        for (int j = 0; j < 4; j++)
            #pragma unroll
            for (int q = 0; q < 4; q++) acc[i][j][q] = 0.f;

    CPA_WAIT0();
    __syncthreads();
    mma_half<4>(smc, wm * 64, wn * 32, lane, 0, acc);
    __syncthreads();
    stageW_cpa(Wsrc, 1, sb, tid); CPA_COMMIT(); CPA_WAIT0();
    __syncthreads();
    mma_half<4>(smc, wm * 64, wn * 32, lane, 4, acc);
    epi_main(smc, sb, acc, tid, wm, wn, g, tg, row0, M, gb4, pre, post, relu,
             wv2, wob, dot, outF, writeA, nextW);
    __syncthreads();
}

// ---------------- K1: fused pred head ----------------------------------------
__global__ void __launch_bounds__(256, 2) k_pred(
    const float* actors, const float* pg1, const float* pb1,
    const float* pg2, const float* pb2, const float* pbo, int N)
{
    extern __shared__ char smc[];
    float4* gb0 = (float4*)smc;
    float4* gb1 = (float4*)(smc + 1024);
    float2* bias2 = (float2*)(smc + 4096);
    const u32 sb = smem_u32p(smc);
    const int tid = threadIdx.x;
    const int y = blockIdx.y, row0 = blockIdx.x * 128;

    stageA_cpa(sb, tid, blockIdx.x);
    stageW_cpa(WSPU + y * 16384, 0, sb, tid);
    CPA_COMMIT();

    if (tid < 64) {
        int c = 2 * tid;
        gb0[tid] = make_float4(pg1[y*128+c], pb1[y*128+c], pg1[y*128+c+1], pb1[y*128+c+1]);
        gb1[tid] = make_float4(pg2[y*128+c], pb2[y*128+c], pg2[y*128+c+1], pb2[y*128+c+1]);
    }
    if (tid < 32) {
        int c = 2 * tid;
        bias2[tid] = make_float2(c < 60 ? pbo[y*60+c] : 0.f, c+1 < 60 ? pbo[y*60+c+1] : 0.f);
    }

    stage128(smc, sb, WSPU + y * 16384, WSPU + (6 + y) * 16384, tid, row0, N,
             gb0, nullptr, nullptr, 1, nullptr, nullptr, nullptr, nullptr, 1);
    stage128(smc, sb, WSPU + (6 + y) * 16384, WOSPU + y * 16384, tid, row0, N,
             gb1, nullptr, actors, 1, nullptr, nullptr, nullptr, nullptr, 1);

    // stage 2: preds = h @ Wo + bias (64-wide, cols 0..59 valid)
    {
        const int wid = tid >> 5, lane = tid & 31;
        const int g = lane >> 2, tg = lane & 3;
        const int rbase = (wid >> 1) * 32, nbase = (wid & 1) * 32;
        float acc[2][4][4];
        #pragma unroll
        for (int i = 0; i < 2; i++)
            #pragma unroll
            for (int j = 0; j < 4; j++)
                #pragma unroll
                for (int q = 0; q < 4; q++) acc[i][j][q] = 0.f;
        CPA_WAIT0();
        __syncthreads();
        mma_half<2>(smc, rbase, nbase, lane, 0, acc);
        __syncthreads();
        stageW_cpa(WOSPU + y * 16384, 1, sb, tid); CPA_COMMIT(); CPA_WAIT0();
        __syncthreads();
        mma_half<2>(smc, rbase, nbase, lane, 4, acc);
        #pragma unroll
        for (int mt = 0; mt < 2; mt++)
        #pragma unroll
        for (int h = 0; h < 2; h++) {
            int R = row0 + rbase + mt * 16 + g + 8 * h;
            if (R < N) {
                float* o = S3 + (size_t)R * 360 + y * 60;
                #pragma unroll
                for (int nt = 0; nt < 4; nt++) {
                    int c = nbase + nt * 8 + tg * 2;
                    if (c < 60) {
                        float2 bb = bias2[c >> 1];
                        o[c]     = acc[mt][nt][2*h]   + bb.x;
                        o[c + 1] = acc[mt][nt][2*h+1] + bb.y;
                    }
                }
            }
        }
    }
}

// ---------------- K2: actB = actors @ agt_W[128:256] -------------------------
__global__ void __launch_bounds__(256, 2) k_actB(int N)
{
    extern __shared__ char smc[];
    const u32 sb = smem_u32p(smc);
    const int tid = threadIdx.x;
    const int row0 = blockIdx.x * 128;

    stageA_cpa(sb, tid, blockIdx.x);
    stageW_cpa(WSPU + 14 * 16384, 0, sb, tid);
    CPA_COMMIT();

    stage128(smc, sb, WSPU + 14 * 16384, nullptr, tid, row0, N,
             nullptr, nullptr, nullptr, 0, nullptr, nullptr, nullptr, S5, 0);
}

// ---------------- K3: fused chain (dist -> agt -> cls1 -> cls2) --------------
__global__ void __launch_bounds__(256, 2) k_chain(
    const float* dW0, const float* db0, const float* dg1, const float* db1v,
    const float* ag, const float* ab, const float* cg1, const float* cb1,
    const float* cg2, const float* cb2, const float* cWo, const float* cbo,
    float* feats, int M)
{
    extern __shared__ char smc[];
    float4* gbA = (float4*)smc;
    float4* gbB = (float4*)(smc + 1024);
    float4* gbC = (float4*)(smc + 2048);
    float4* gbD = (float4*)(smc + 3072);
    float2* wv2 = (float2*)(smc + 4096);
    float* w0a = (float*)(smc + 4608);
    float* w0b = (float*)(smc + 5120);
    float* b0v = (float*)(smc + 5632);
    float* pav = (float*)(smc + 6144);
    float* pbv = (float*)(smc + 6656);
    u32* Ahi = (u32*)(smc + OF_AH); u32* Alo = (u32*)(smc + OF_AL);
    const u32 sb = smem_u32p(smc);

    const int tid = threadIdx.x;
    const int row0 = blockIdx.x * 128;

    stageW_cpa(WSPU + 12 * 16384, 0, sb, tid);
    CPA_COMMIT();

    if (tid < 64) {
        int c = 2 * tid;
        gbA[tid] = make_float4(dg1[c], db1v[c], dg1[c+1], db1v[c+1]);
        gbB[tid] = make_float4(ag[c],  ab[c],   ag[c+1],  ab[c+1]);
        gbC[tid] = make_float4(cg1[c], cb1[c],  cg1[c+1], cb1[c+1]);
        gbD[tid] = make_float4(cg2[c], cb2[c],  cg2[c+1], cb2[c+1]);
        wv2[tid] = make_float2(cWo[c], cWo[c+1]);
    }
    if (tid < 128) {
        w0a[tid] = dW0[tid]; w0b[tid] = dW0[128 + tid]; b0v[tid] = db0[tid];
        int R = row0 + tid; float a = 0.f, bq = 0.f;
        if (R < M) { a = S3[(size_t)R * 60 + 58]; bq = S3[(size_t)R * 60 + 59]; }
        pav[tid] = a; pbv[tid] = bq;
    }
    __syncthreads();

    // generate dist A in fragment layout: relu(b0 - p58*W0[0] - p59*W0[1])
    #pragma unroll
    for (int it = 0; it < 32; it++) {
        int idx = tid + it * 256;                 // 8192 = 128 rows x 64 pairs
        int r = idx >> 6, p = idx & 63;
        int k2 = 2 * p;
        float x0 = fmaxf(b0v[k2]     - pav[r] * w0a[k2]     - pbv[r] * w0b[k2],     0.f);
        float x1 = fmaxf(b0v[k2 + 1] - pav[r] * w0a[k2 + 1] - pbv[r] * w0b[k2 + 1], 0.f);
        u32 p0 = packbf(x0), p1 = packbf(x1);
        int r16 = r >> 4, rq = r & 15, h = rq >> 3, gg = rq & 7;
        int ks = p >> 3, pin = p & 7, kj = pin >> 2, tg = pin & 3;
        int lane = gg * 4 + tg; lane ^= (lane >> 3);
        u32 off = (u32)(r16 * 8 + ks) * 128 + lane * 4 + h + 2 * kj;
        Ahi[off] = (p0 >> 16) | (p1 & 0xffff0000u);
        Alo[off] = (p0 & 0xffffu) | (p1 << 16);
    }

    stage128(smc, sb, WSPU + 12 * 16384, WSPU + 13 * 16384, tid, row0, M,
             gbA, nullptr, nullptr, 1, nullptr, nullptr, nullptr, nullptr, 1);
    stage128(smc, sb, WSPU + 13 * 16384, WSPU + 15 * 16384, tid, row0, M,
             gbB, S5, nullptr, 1, nullptr, nullptr, nullptr, feats, 1);
    stage128(smc, sb, WSPU + 15 * 16384, WSPU + 16 * 16384, tid, row0, M,
             gbC, nullptr, nullptr, 1, nullptr, nullptr, nullptr, nullptr, 1);
    stage128(smc, sb, WSPU + 16 * 16384, nullptr, tid, row0, M,
             gbD, nullptr, feats, 1, wv2, cbo, S4, nullptr, 0);
}

// ---------------- softmax + rank-sort + reg gather ---------------------------
__global__ void finalize(const float* ctr, float* clsO, float* regO, int N)
{
    int w = (blockIdx.x * blockDim.x + threadIdx.x) >> 5;
    int lane = threadIdx.x & 31;
    if (w >= N) return;
    float v = (lane < 6) ? S4[(size_t)w * 6 + lane] : -3.4e38f;
    float m = v;
    #pragma unroll
    for (int s = 4; s >= 1; s >>= 1) m = fmaxf(m, __shfl_xor_sync(~0u, m, s));
    float e = (lane < 6) ? expf(v - m) : 0.f;
    float s = e;
    #pragma unroll
    for (int t = 4; t >= 1; t >>= 1) s += __shfl_xor_sync(~0u, s, t);
    float pr = e / s;
    int rk = 0;
    #pragma unroll
    for (int j = 0; j < 6; j++) {
        float pj = __shfl_sync(~0u, pr, j);
        rk += (pj > pr) || (pj == pr && j < lane);
    }
    if (lane < 6) clsO[(size_t)w * 6 + rk] = pr;
    float cx = ctr[(size_t)w * 2], cy = ctr[(size_t)w * 2 + 1];
    for (int k = 0; k < 6; k++) {
        int r = __shfl_sync(~0u, rk, k);
        const float* sp = S3 + (size_t)w * 360 + k * 60;
        float* dp = regO + ((size_t)w * 6 + r) * 60;
        for (int j = lane; j < 60; j += 32) dp[j] = sp[j] + ((j & 1) ? cy : cx);
    }
}

// ---------------- host orchestration ----------------------------------------
extern "C" void kernel_launch(void* const* d_in, const int* in_sizes, int n_in,
                              void* d_out, int out_size)
{
    const float* actors = (const float*)d_in[0];
    const float* ctrs   = (const float*)d_in[1];
    const float* pW1 = (const float*)d_in[2];
    const float* pg1 = (const float*)d_in[3];
    const float* pb1 = (const float*)d_in[4];
    const float* pW2 = (const float*)d_in[5];
    const float* pg2 = (const float*)d_in[6];
    const float* pb2 = (const float*)d_in[7];
    const float* pWo = (const float*)d_in[8];
    const float* pbo = (const float*)d_in[9];
    const float* dW0 = (const float*)d_in[10];
    const float* db0 = (const float*)d_in[11];
    const float* dW1 = (const float*)d_in[12];
    const float* dg1 = (const float*)d_in[13];
    const float* db1 = (const float*)d_in[14];
    const float* aW  = (const float*)d_in[15];
    const float* ag  = (const float*)d_in[16];
    const float* ab  = (const float*)d_in[17];
    const float* cW1 = (const float*)d_in[18];
    const float* cg1 = (const float*)d_in[19];
    const float* cb1 = (const float*)d_in[20];
    const float* cW2 = (const float*)d_in[21];
    const float* cg2 = (const float*)d_in[22];
    const float* cb2 = (const float*)d_in[23];
    const float* cWo = (const float*)d_in[24];
    const float* cbo = (const float*)d_in[25];

    const int N = in_sizes[0] / 128;       // 100000
    const int M = N * 6;
    const int gN = (N + 127) / 128, gM = (M + 127) / 128;
    float* out   = (float*)d_out;
    float* regO  = out + (size_t)N * 6;
    float* feats = regO + (size_t)N * 360;

    cudaFuncSetAttribute(k_pred,  cudaFuncAttributeMaxDynamicSharedMemorySize, SMEMB);
    cudaFuncSetAttribute(k_actB,  cudaFuncAttributeMaxDynamicSharedMemorySize, SMEMB);
    cudaFuncSetAttribute(k_chain, cudaFuncAttributeMaxDynamicSharedMemorySize, SMEMB);

    prep_w<<<17, 256>>>(pW1, pW2, dW1, aW, cW1, cW2);
    prep_wo<<<6, 256>>>(pWo);
    prep_x<<<(gN * 8192 + 255) / 256, 256>>>(actors, N, gN);

    k_pred<<<dim3(gN, 6), 256, SMEMB>>>(actors, pg1, pb1, pg2, pb2, pbo, N);
    k_actB<<<gN, 256, SMEMB>>>(N);
    k_chain<<<gM, 256, SMEMB>>>(dW0, db0, dg1, db1, ag, ab, cg1, cb1,
                                cg2, cb2, cWo, cbo, feats, M);
    finalize<<<(N + 7) / 8, 256>>>(ctrs, out, regO, N);
}